// round 10
// baseline (speedup 1.0000x reference)
#include <cuda_runtime.h>
#include <cuda_bf16.h>
#include <stdint.h>

#define Dd 128
#define Ll 200
#define Bb 4096
#define NITEMS 100000

// Scratch (static device globals: allocation-free per harness rules)
__device__ __nv_bfloat16 g_KWh[(NITEMS + 1) * Dd];  // item_emb @ Wk (bf16)
__device__ __nv_bfloat16 g_Ih[(NITEMS + 1) * Dd];   // item_emb in bf16 (GEMM input only)
__device__ float g_Q[Bb * Dd];                      // Q = u@Wq + b_att (fp32)
__device__ float g_F1[Bb * Ll];                     // exp(0.1*eps1)
__device__ float g_F2[Bb * Ll];                     // exp(0.1*eps2)
__device__ float g_klp[Bb];
__device__ int   g_cnt[Bb];

// ---------------------------------------------------------------- utilities

__device__ __forceinline__ uint32_t rotl32(uint32_t x, int d) {
    return (x << d) | (x >> (32 - d));
}

// Exact JAX threefry2x32 (20 rounds)
__device__ __forceinline__ void threefry2x32(uint32_t k0, uint32_t k1,
                                             uint32_t c0, uint32_t c1,
                                             uint32_t& o0, uint32_t& o1) {
    uint32_t ks2 = k0 ^ k1 ^ 0x1BD11BDAu;
    uint32_t x0 = c0 + k0, x1 = c1 + k1;
#define TF_R(r) { x0 += x1; x1 = rotl32(x1, r); x1 ^= x0; }
    TF_R(13) TF_R(15) TF_R(26) TF_R(6)  x0 += k1;  x1 += ks2 + 1u;
    TF_R(17) TF_R(29) TF_R(16) TF_R(24) x0 += ks2; x1 += k0 + 2u;
    TF_R(13) TF_R(15) TF_R(26) TF_R(6)  x0 += k0;  x1 += k1 + 3u;
    TF_R(17) TF_R(29) TF_R(16) TF_R(24) x0 += k1;  x1 += ks2 + 4u;
    TF_R(13) TF_R(15) TF_R(26) TF_R(6)  x0 += ks2; x1 += k0 + 5u;
#undef TF_R
    o0 = x0; o1 = x1;
}

// jax.random.normal under jax_threefry_partitionable=True:
//   counter = 64-bit flat index -> (c0 = 0, c1 = idx); 32-bit draw = o0 ^ o1
__device__ __forceinline__ float jax_normal(uint32_t k1, uint32_t idx) {
    uint32_t o0, o1;
    threefry2x32(0u, k1, 0u, idx, o0, o1);
    uint32_t bits = o0 ^ o1;
    float f = __uint_as_float((bits >> 9) | 0x3F800000u) - 1.0f;  // [0,1)
    const float LO = -0.99999994f;                                // nextafter(-1,0)
    float u = fmaf(f, 2.0f, LO);
    u = fmaxf(u, LO);
    return 1.41421356f * erfinvf(u);
}

__device__ __forceinline__ float fast_tanh(float x) {
    float y;
    asm("tanh.approx.f32 %0, %1;" : "=f"(y) : "f"(x));
    return y;
}

__device__ __forceinline__ float breduce_sum(float v, volatile float* red) {
    int tid = threadIdx.x, lane = tid & 31, wrp = tid >> 5;
#pragma unroll
    for (int o = 16; o; o >>= 1) v += __shfl_down_sync(0xffffffffu, v, o);
    if (lane == 0) red[wrp] = v;
    __syncthreads();
    float r = (red[0] + red[1]) + (red[2] + red[3]);
    __syncthreads();
    return r;
}

__device__ __forceinline__ float breduce_max(float v, volatile float* red) {
    int tid = threadIdx.x, lane = tid & 31, wrp = tid >> 5;
#pragma unroll
    for (int o = 16; o; o >>= 1) v = fmaxf(v, __shfl_down_sync(0xffffffffu, v, o));
    if (lane == 0) red[wrp] = v;
    __syncthreads();
    float r = fmaxf(fmaxf(red[0], red[1]), fmaxf(red[2], red[3]));
    __syncthreads();
    return r;
}

// 3-value block sum in one sync round
__device__ __forceinline__ void breduce_sum3(float& a, float& b, float& c,
                                             volatile float* red12) {
    int tid = threadIdx.x, lane = tid & 31, wrp = tid >> 5;
#pragma unroll
    for (int o = 16; o; o >>= 1) {
        a += __shfl_down_sync(0xffffffffu, a, o);
        b += __shfl_down_sync(0xffffffffu, b, o);
        c += __shfl_down_sync(0xffffffffu, c, o);
    }
    if (lane == 0) {
        red12[wrp * 3 + 0] = a;
        red12[wrp * 3 + 1] = b;
        red12[wrp * 3 + 2] = c;
    }
    __syncthreads();
    a = (red12[0] + red12[3]) + (red12[6] + red12[9]);
    b = (red12[1] + red12[4]) + (red12[7] + red12[10]);
    c = (red12[2] + red12[5]) + (red12[8] + red12[11]);
    __syncthreads();
}

// ------------------------------------------- Kernel 0: item_emb -> bf16 table
__global__ __launch_bounds__(256) void conv_item_kernel(const float* __restrict__ item_emb) {
    const int total = (NITEMS + 1) * (Dd / 4);          // float4 count
    for (int i = blockIdx.x * 256 + threadIdx.x; i < total; i += gridDim.x * 256) {
        float4 v = ((const float4*)item_emb)[i];
        __nv_bfloat162 lo = __floats2bfloat162_rn(v.x, v.y);
        __nv_bfloat162 hi = __floats2bfloat162_rn(v.z, v.w);
        uint2 p;
        p.x = *(uint32_t*)&lo;
        p.y = *(uint32_t*)&hi;
        ((uint2*)g_Ih)[i] = p;
    }
}

// ------------------------------------------- Kernel E: precompute lognormal factors
__global__ __launch_bounds__(256) void eps_kernel() {
    int idx = blockIdx.x * 256 + threadIdx.x;
    if (idx < Bb * Ll) {
        float e1 = jax_normal(1u, (uint32_t)idx);
        float e2 = jax_normal(2u, (uint32_t)idx);
        g_F1[idx] = expf(0.1f * e1);
        g_F2[idx] = expf(0.1f * e2);
    }
}

// =================================================================
// bf16 m16n8k16 MMA; smem tiles: uint32 k-pairs, row stride PADU uint32
// =================================================================
#define PADU 68

// ------------------------------------------- Kernel A: KW = item_emb @ Wk (bf16 MMA)
#define KW_GRID 148
#define KW_TILES ((NITEMS + 1 + 127) / 128)   // 782

__global__ __launch_bounds__(256, 2) void kw_kernel(const float* __restrict__ Wk) {
    extern __shared__ uint32_t smem_u[];
    uint32_t* sW  = smem_u;                    // [128 n][68]
    uint32_t* sA0 = smem_u + 128 * PADU;
    uint32_t* sA1 = sA0 + 128 * PADU;

    const int tid  = threadIdx.x;
    const int lane = tid & 31;
    const int wid  = tid >> 5;
    const int gid  = lane >> 2;      // 0..7
    const int tig  = lane & 3;       // 0..3
    const int stripe = (wid & 3) * 32;
    const int colh   = (wid >> 2) * 64;

    // sW[n][p] = {bf16(Wk[2p][n]), bf16(Wk[2p+1][n])} — coalesced fill
#pragma unroll 8
    for (int i = tid; i < 64 * 128; i += 256) {
        int p = i >> 7, n = i & 127;
        float a = Wk[(2 * p) * Dd + n];
        float b = Wk[(2 * p + 1) * Dd + n];
        __nv_bfloat162 h = __floats2bfloat162_rn(a, b);
        sW[n * PADU + p] = *(uint32_t*)&h;
    }

    uint32_t* bufs[2] = { sA0, sA1 };
    int cur = 0;
    int t = blockIdx.x;

#define LOAD_TILE(dst, tt) do {                                               \
        const int row0_ = (tt) * 128;                                         \
        for (int i = tid; i < 128 * 16; i += 256) {                           \
            int r_ = i >> 4, c_ = i & 15;                                     \
            int sr_ = row0_ + r_; if (sr_ > NITEMS) sr_ = NITEMS;             \
            const char* src_ = (const char*)g_Ih + (size_t)sr_ * 256 + c_ * 16;\
            uint32_t d_ = (uint32_t)__cvta_generic_to_shared(                 \
                              (dst) + r_ * PADU + c_ * 4);                    \
            asm volatile("cp.async.ca.shared.global [%0], [%1], 16;\n"        \
                         :: "r"(d_), "l"(src_));                              \
        }                                                                     \
    } while (0)

    if (t < KW_TILES) LOAD_TILE(bufs[0], t);
    asm volatile("cp.async.commit_group;\n");

    while (t < KW_TILES) {
        int tn = t + KW_GRID;
        if (tn < KW_TILES) LOAD_TILE(bufs[cur ^ 1], tn);
        asm volatile("cp.async.commit_group;\n");
        asm volatile("cp.async.wait_group 1;\n");
        __syncthreads();

        uint32_t* sA = bufs[cur];
        float acc[2][8][4];
#pragma unroll
        for (int mi = 0; mi < 2; mi++)
#pragma unroll
            for (int ni = 0; ni < 8; ni++)
#pragma unroll
                for (int j = 0; j < 4; j++) acc[mi][ni][j] = 0.f;

#pragma unroll
        for (int ks = 0; ks < 8; ks++) {
            const int p0 = ks * 8;
            uint32_t a[2][4];
#pragma unroll
            for (int mi = 0; mi < 2; mi++) {
                int r = stripe + mi * 16 + gid;
                a[mi][0] = sA[r * PADU + p0 + tig];
                a[mi][1] = sA[(r + 8) * PADU + p0 + tig];
                a[mi][2] = sA[r * PADU + p0 + tig + 4];
                a[mi][3] = sA[(r + 8) * PADU + p0 + tig + 4];
            }
            uint32_t bf[8][2];
#pragma unroll
            for (int ni = 0; ni < 8; ni++) {
                int n = colh + ni * 8 + gid;
                bf[ni][0] = sW[n * PADU + p0 + tig];
                bf[ni][1] = sW[n * PADU + p0 + tig + 4];
            }
#pragma unroll
            for (int mi = 0; mi < 2; mi++)
#pragma unroll
                for (int ni = 0; ni < 8; ni++) {
                    asm volatile(
                        "mma.sync.aligned.m16n8k16.row.col.f32.bf16.bf16.f32 "
                        "{%0,%1,%2,%3}, {%4,%5,%6,%7}, {%8,%9}, {%0,%1,%2,%3};"
                        : "+f"(acc[mi][ni][0]), "+f"(acc[mi][ni][1]),
                          "+f"(acc[mi][ni][2]), "+f"(acc[mi][ni][3])
                        : "r"(a[mi][0]), "r"(a[mi][1]), "r"(a[mi][2]), "r"(a[mi][3]),
                          "r"(bf[ni][0]), "r"(bf[ni][1]));
                }
        }

        // epilogue: bf16 pack + store
        const int row0 = t * 128;
        uint32_t* kw32 = (uint32_t*)g_KWh;
#pragma unroll
        for (int mi = 0; mi < 2; mi++) {
            int r0 = row0 + stripe + mi * 16 + gid;
            int r1 = r0 + 8;
#pragma unroll
            for (int ni = 0; ni < 8; ni++) {
                int c = colh + ni * 8 + tig * 2;
                if (r0 <= NITEMS) {
                    __nv_bfloat162 h = __floats2bfloat162_rn(acc[mi][ni][0], acc[mi][ni][1]);
                    kw32[(size_t)r0 * (Dd / 2) + (c >> 1)] = *(uint32_t*)&h;
                }
                if (r1 <= NITEMS) {
                    __nv_bfloat162 h = __floats2bfloat162_rn(acc[mi][ni][2], acc[mi][ni][3]);
                    kw32[(size_t)r1 * (Dd / 2) + (c >> 1)] = *(uint32_t*)&h;
                }
            }
        }
        __syncthreads();
        cur ^= 1;
        t = tn;
    }
#undef LOAD_TILE
}

// ------------------------------------------- Kernel B: Q = user_emb[uidx] @ Wq + b_att
__global__ __launch_bounds__(256) void q_kernel(const float* __restrict__ user_emb,
                                                const int* __restrict__ user_idx,
                                                const float* __restrict__ Wq,
                                                const float* __restrict__ b_att) {
    extern __shared__ uint32_t smem_u[];
    uint32_t* sW = smem_u;                 // [128 n][68]
    uint32_t* sA = smem_u + 128 * PADU;    // [32 m][68]

    const int tid  = threadIdx.x;
    const int lane = tid & 31;
    const int wid  = tid >> 5;
    const int gid  = lane >> 2;
    const int tig  = lane & 3;
    const int mrow = (wid & 1) * 16;
    const int ncol = (wid >> 1) * 32;
    const int row0 = blockIdx.x * 32;

#pragma unroll 8
    for (int i = tid; i < 64 * 128; i += 256) {
        int p = i >> 7, n = i & 127;
        float a = Wq[(2 * p) * Dd + n];
        float b = Wq[(2 * p + 1) * Dd + n];
        __nv_bfloat162 h = __floats2bfloat162_rn(a, b);
        sW[n * PADU + p] = *(uint32_t*)&h;
    }
#pragma unroll
    for (int i = tid; i < 32 * 64; i += 256) {
        int r = i >> 6, p = i & 63;
        int u = user_idx[row0 + r];
        float2 v = *(const float2*)(user_emb + (size_t)u * Dd + 2 * p);
        __nv_bfloat162 h = __floats2bfloat162_rn(v.x, v.y);
        sA[r * PADU + p] = *(uint32_t*)&h;
    }
    __syncthreads();

    float acc[4][4];
#pragma unroll
    for (int ni = 0; ni < 4; ni++)
#pragma unroll
        for (int j = 0; j < 4; j++) acc[ni][j] = 0.f;

#pragma unroll
    for (int ks = 0; ks < 8; ks++) {
        const int p0 = ks * 8;
        uint32_t a[4];
        a[0] = sA[(mrow + gid) * PADU + p0 + tig];
        a[1] = sA[(mrow + 8 + gid) * PADU + p0 + tig];
        a[2] = sA[(mrow + gid) * PADU + p0 + tig + 4];
        a[3] = sA[(mrow + 8 + gid) * PADU + p0 + tig + 4];
        uint32_t bf[4][2];
#pragma unroll
        for (int ni = 0; ni < 4; ni++) {
            int n = ncol + ni * 8 + gid;
            bf[ni][0] = sW[n * PADU + p0 + tig];
            bf[ni][1] = sW[n * PADU + p0 + tig + 4];
        }
#pragma unroll
        for (int ni = 0; ni < 4; ni++) {
            asm volatile(
                "mma.sync.aligned.m16n8k16.row.col.f32.bf16.bf16.f32 "
                "{%0,%1,%2,%3}, {%4,%5,%6,%7}, {%8,%9}, {%0,%1,%2,%3};"
                : "+f"(acc[ni][0]), "+f"(acc[ni][1]),
                  "+f"(acc[ni][2]), "+f"(acc[ni][3])
                : "r"(a[0]), "r"(a[1]), "r"(a[2]), "r"(a[3]),
                  "r"(bf[ni][0]), "r"(bf[ni][1]));
        }
    }

    {
        int r0 = row0 + mrow + gid;
        int r1 = r0 + 8;
#pragma unroll
        for (int ni = 0; ni < 4; ni++) {
            int c = ncol + ni * 8 + tig * 2;
            float2 ba = *(const float2*)(b_att + c);
            *(float2*)(g_Q + (size_t)r0 * Dd + c) =
                make_float2(acc[ni][0] + ba.x, acc[ni][1] + ba.y);
            *(float2*)(g_Q + (size_t)r1 * Dd + c) =
                make_float2(acc[ni][2] + ba.x, acc[ni][3] + ba.y);
        }
    }
}

// ------------------------------------------- Kernel C: fused BAM forward
__global__ __launch_bounds__(128, 8) void fused_kernel(
    const float* __restrict__ user_emb,
    const float* __restrict__ item_emb,
    const float* __restrict__ v_att,
    const float* __restrict__ ln_u_g, const float* __restrict__ ln_u_b,
    const float* __restrict__ ln_i_g, const float* __restrict__ ln_i_b,
    const float* __restrict__ pred_W, const float* __restrict__ pred_b,
    const int* __restrict__ user_hist,
    const int* __restrict__ user_idx,
    const int* __restrict__ item_idx,
    float* __restrict__ out)
{
    __shared__ __align__(16) float sh_q[Dd];
    __shared__ __align__(16) float sh_u[Dd];
    __shared__ __align__(16) float sh_v[Dd];
    __shared__ int   sh_r[Ll];
    __shared__ float sh_s[Ll];
    __shared__ float sh_w1[Ll];
    __shared__ float sh_w2[Ll];
    __shared__ float red[12];

    const int tid  = threadIdx.x;
    const int lane = tid & 31;
    const int wrp  = tid >> 5;
    const int b    = blockIdx.x;
    const int uidx = user_idx[b];
    const int tgt  = item_idx[b];

    sh_u[tid] = user_emb[(size_t)uidx * Dd + tid];
    sh_q[tid] = g_Q[(size_t)b * Dd + tid];     // includes b_att
    sh_v[tid] = v_att[tid];
    float validf = 0.f;
    for (int l = tid; l < Ll; l += 128) {
        int r = user_hist[(size_t)uidx * Ll + l];
        bool ok = (r != tgt) && (r != NITEMS);
        sh_r[l] = ok ? r : -1;
        validf += ok ? 1.f : 0.f;
    }
    __syncthreads();

    float nvf = breduce_sum(validf, red);
    int n_valid = (int)(nvf + 0.5f);
    float nv_clamped = (n_valid > 0) ? (float)n_valid : 1.0f;
    float mu_p = -logf(nv_clamped);

    // scores: warp per l, 4 rows/iteration (MLP=4); lane covers 4 dims (8B bf16).
    // While scoring row r we also L2-prefetch its fp32 item row for the
    // context gather that runs ~2k cycles later.
    float4 q4, v4;
    {
        float2 qa = *(const float2*)(sh_q + lane * 4);
        float2 qb = *(const float2*)(sh_q + lane * 4 + 2);
        q4 = make_float4(qa.x, qa.y, qb.x, qb.y);
        float2 va = *(const float2*)(sh_v + lane * 4);
        float2 vb = *(const float2*)(sh_v + lane * 4 + 2);
        v4 = make_float4(va.x, va.y, vb.x, vb.y);
    }
    for (int l = wrp; l < Ll; l += 16) {
        int ls[4], rs[4];
        uint2 raws[4];
#pragma unroll
        for (int j = 0; j < 4; j++) {
            ls[j] = l + j * 4;
            rs[j] = (ls[j] < Ll) ? sh_r[ls[j]] : -1;
        }
#pragma unroll
        for (int j = 0; j < 4; j++) {
            raws[j] = make_uint2(0u, 0u);
            if (rs[j] >= 0)
                raws[j] = ((const uint2*)(g_KWh + (size_t)rs[j] * Dd))[lane];
        }
        // L2 prefetch of the fp32 item rows (lanes 0..3 cover the 512B row)
#pragma unroll
        for (int j = 0; j < 4; j++) {
            if (rs[j] >= 0 && lane < 4) {
                const float* p = item_emb + (size_t)rs[j] * Dd + lane * 32;
                asm volatile("prefetch.global.L2 [%0];" :: "l"(p));
            }
        }
#pragma unroll
        for (int j = 0; j < 4; j++) {
            if (ls[j] >= Ll) break;
            float sval = -1e30f;
            if (rs[j] >= 0) {
                float2 f0 = __bfloat1622float2(*(__nv_bfloat162*)&raws[j].x);
                float2 f1 = __bfloat1622float2(*(__nv_bfloat162*)&raws[j].y);
                float tv = v4.x * fast_tanh(q4.x + f0.x);
                tv = fmaf(v4.y, fast_tanh(q4.y + f0.y), tv);
                tv = fmaf(v4.z, fast_tanh(q4.z + f1.x), tv);
                tv = fmaf(v4.w, fast_tanh(q4.w + f1.y), tv);
#pragma unroll
                for (int o = 16; o; o >>= 1)
                    tv += __shfl_down_sync(0xffffffffu, tv, o);
                sval = tv * 0.25f;   // / TAU
            }
            if (lane == 0) sh_s[ls[j]] = sval;
        }
    }
    __syncthreads();

    // softmax
    float m = -1e30f;
    for (int l = tid; l < Ll; l += 128) m = fmaxf(m, sh_s[l]);
    m = breduce_max(m, red);

    float esum = 0.f;
    for (int l = tid; l < Ll; l += 128) {
        float e = 0.f;
        if (sh_r[l] >= 0) e = expf(sh_s[l] - m);
        sh_s[l] = e;
        esum += e;
    }
    esum = breduce_sum(esum, red);
    float inv_es = (esum > 0.f) ? (1.0f / esum) : 0.f;

    // sampled weights via precomputed lognormal factors + KL; triple reduce
    float klacc = 0.f, s1 = 0.f, s2 = 0.f;
    for (int l = tid; l < Ll; l += 128) {
        float w1 = 0.f, w2 = 0.f;
        if (sh_r[l] >= 0) {
            float alpha = sh_s[l] * inv_es;
            float ap = alpha + 1e-24f;
            float mu = logf(ap);
            int idx = b * Ll + l;
            w1 = ap * g_F1[idx];
            w2 = ap * g_F2[idx];
            float dmu = mu - mu_p;
            klacc += 1.8075851f + 0.5f * dmu * dmu;  // log(10)-0.5+SIG_Q^2/2 + d^2/2
        }
        sh_w1[l] = w1;
        sh_w2[l] = w2;
        s1 += w1;
        s2 += w2;
    }
    breduce_sum3(klacc, s1, s2, red);
    if (tid == 0) { g_klp[b] = klacc; g_cnt[b] = n_valid; }
    float i1 = 1.0f / (s1 + 1e-12f);
    float i2 = 1.0f / (s2 + 1e-12f);

    // contexts: fp32 item_emb gather (value path stays fp32),
    // 8 batched loads per group (MLP=8); one gather serves both draws
    float cu = 0.f, ci = 0.f;
    for (int l0 = 0; l0 < Ll; l0 += 8) {
        float vv[8];
#pragma unroll
        for (int j = 0; j < 8; j++) {
            int r = sh_r[l0 + j];
            vv[j] = (r >= 0) ? item_emb[(size_t)r * Dd + tid] : 0.f;
        }
#pragma unroll
        for (int j = 0; j < 8; j++) {
            cu = fmaf(sh_w1[l0 + j], vv[j], cu);
            ci = fmaf(sh_w2[l0 + j], vv[j], ci);
        }
    }
    cu *= i1; ci *= i2;

    // layernorm(u ctx * user_emb)
    float xu = cu * sh_u[tid];
    float mean_u = breduce_sum(xu, red) * (1.0f / Dd);
    float du = xu - mean_u;
    float var_u = breduce_sum(du * du, red) * (1.0f / Dd);
    float us = du * rsqrtf(var_u + 1e-5f) * ln_u_g[tid] + ln_u_b[tid];

    // layernorm(i ctx * item_emb[target])
    float xi = ci * item_emb[(size_t)tgt * Dd + tid];
    float mean_i = breduce_sum(xi, red) * (1.0f / Dd);
    float di = xi - mean_i;
    float var_i = breduce_sum(di * di, red) * (1.0f / Dd);
    float is_ = di * rsqrtf(var_i + 1e-5f) * ln_i_g[tid] + ln_i_b[tid];

    float pv = us * is_ * pred_W[tid];
    float dot = breduce_sum(pv, red);
    if (tid == 0) out[b] = dot + pred_b[0];
}

// ------------------------------------------- Kernel D: deterministic KL reduce
__global__ __launch_bounds__(256) void kl_reduce_kernel(float* __restrict__ out,
                                                        int out_size) {
    __shared__ float rs[8];
    __shared__ int   ri[8];
    int tid = threadIdx.x;
    float s = 0.f; int c = 0;
    for (int i = tid; i < Bb; i += 256) { s += g_klp[i]; c += g_cnt[i]; }
#pragma unroll
    for (int o = 16; o; o >>= 1) {
        s += __shfl_down_sync(0xffffffffu, s, o);
        c += __shfl_down_sync(0xffffffffu, c, o);
    }
    if ((tid & 31) == 0) { rs[tid >> 5] = s; ri[tid >> 5] = c; }
    __syncthreads();
    if (tid == 0) {
        float S = 0.f; int C = 0;
        for (int i = 0; i < 8; i++) { S += rs[i]; C += ri[i]; }
        if (C < 1) C = 1;
        float kl = 0.25f * S / (float)C;   // BETA * sum / cnt ; (kl_u+kl_i)/2 == kl_u
        if (out_size > Bb) out[Bb] = kl;
    }
}

// ------------------------------------------- launcher
extern "C" void kernel_launch(void* const* d_in, const int* in_sizes, int n_in,
                              void* d_out, int out_size) {
    const float* user_emb = (const float*)d_in[0];
    const float* item_emb = (const float*)d_in[1];
    const float* Wq       = (const float*)d_in[2];
    const float* Wk       = (const float*)d_in[3];
    const float* b_att    = (const float*)d_in[4];
    const float* v_att    = (const float*)d_in[5];
    const float* ln_u_g   = (const float*)d_in[6];
    const float* ln_u_b   = (const float*)d_in[7];
    const float* ln_i_g   = (const float*)d_in[8];
    const float* ln_i_b   = (const float*)d_in[9];
    const float* pred_W   = (const float*)d_in[10];
    const float* pred_b   = (const float*)d_in[11];
    const int* user_hist  = (const int*)d_in[12];
    const int* user_idx   = (const int*)d_in[13];
    const int* item_idx   = (const int*)d_in[14];
    float* out = (float*)d_out;

    static cudaStream_t s1 = nullptr, s2 = nullptr;
    static cudaEvent_t evRoot = nullptr, ev1 = nullptr, ev2 = nullptr;
    if (s1 == nullptr) {
        cudaStreamCreateWithFlags(&s1, cudaStreamNonBlocking);
        cudaStreamCreateWithFlags(&s2, cudaStreamNonBlocking);
        cudaEventCreateWithFlags(&evRoot, cudaEventDisableTiming);
        cudaEventCreateWithFlags(&ev1, cudaEventDisableTiming);
        cudaEventCreateWithFlags(&ev2, cudaEventDisableTiming);
    }

    const int kw_smem = 3 * 128 * PADU * 4;          // 104448 B
    const int q_smem  = (128 + 32) * PADU * 4;       // 43520 B
    cudaFuncSetAttribute(kw_kernel, cudaFuncAttributeMaxDynamicSharedMemorySize,
                         kw_smem);
    cudaFuncSetAttribute(q_kernel, cudaFuncAttributeMaxDynamicSharedMemorySize,
                         q_smem);

    // fork: eps on s1, q on s2, conv+kw on main stream
    cudaEventRecord(evRoot, 0);
    cudaStreamWaitEvent(s1, evRoot, 0);
    cudaStreamWaitEvent(s2, evRoot, 0);

    eps_kernel<<<(Bb * Ll + 255) / 256, 256, 0, s1>>>();
    q_kernel<<<Bb / 32, 256, q_smem, s2>>>(user_emb, user_idx, Wq, b_att);

    conv_item_kernel<<<1184, 256>>>(item_emb);
    kw_kernel<<<KW_GRID, 256, kw_smem>>>(Wk);

    // join
    cudaEventRecord(ev1, s1);
    cudaEventRecord(ev2, s2);
    cudaStreamWaitEvent(0, ev1, 0);
    cudaStreamWaitEvent(0, ev2, 0);

    fused_kernel<<<Bb, 128>>>(user_emb, item_emb, v_att,
                              ln_u_g, ln_u_b, ln_i_g, ln_i_b,
                              pred_W, pred_b, user_hist, user_idx, item_idx, out);
    kl_reduce_kernel<<<1, 256>>>(out, out_size);
}

// round 11
// speedup vs baseline: 1.4962x; 1.4962x over previous
#include <cuda_runtime.h>
#include <cuda_bf16.h>
#include <stdint.h>

#define Dd 128
#define Ll 200
#define Bb 4096
#define NITEMS 100000

// Scratch (static device globals: allocation-free per harness rules)
__device__ __nv_bfloat16 g_KWh[(NITEMS + 1) * Dd];  // item_emb @ Wk (bf16)
__device__ __nv_bfloat16 g_Ih[(NITEMS + 1) * Dd];   // item_emb in bf16 (GEMM input only)
__device__ float g_Q[Bb * Dd];                      // Q = u@Wq + b_att (fp32)
__device__ float g_F1[Bb * Ll];                     // exp(0.1*eps1)
__device__ float g_F2[Bb * Ll];                     // exp(0.1*eps2)
__device__ float g_klp[Bb];
__device__ int   g_cnt[Bb];

// ---------------------------------------------------------------- utilities

__device__ __forceinline__ uint32_t rotl32(uint32_t x, int d) {
    return (x << d) | (x >> (32 - d));
}

// Exact JAX threefry2x32 (20 rounds)
__device__ __forceinline__ void threefry2x32(uint32_t k0, uint32_t k1,
                                             uint32_t c0, uint32_t c1,
                                             uint32_t& o0, uint32_t& o1) {
    uint32_t ks2 = k0 ^ k1 ^ 0x1BD11BDAu;
    uint32_t x0 = c0 + k0, x1 = c1 + k1;
#define TF_R(r) { x0 += x1; x1 = rotl32(x1, r); x1 ^= x0; }
    TF_R(13) TF_R(15) TF_R(26) TF_R(6)  x0 += k1;  x1 += ks2 + 1u;
    TF_R(17) TF_R(29) TF_R(16) TF_R(24) x0 += ks2; x1 += k0 + 2u;
    TF_R(13) TF_R(15) TF_R(26) TF_R(6)  x0 += k0;  x1 += k1 + 3u;
    TF_R(17) TF_R(29) TF_R(16) TF_R(24) x0 += k1;  x1 += ks2 + 4u;
    TF_R(13) TF_R(15) TF_R(26) TF_R(6)  x0 += ks2; x1 += k0 + 5u;
#undef TF_R
    o0 = x0; o1 = x1;
}

// jax.random.normal under jax_threefry_partitionable=True:
//   counter = 64-bit flat index -> (c0 = 0, c1 = idx); 32-bit draw = o0 ^ o1
__device__ __forceinline__ float jax_normal(uint32_t k1, uint32_t idx) {
    uint32_t o0, o1;
    threefry2x32(0u, k1, 0u, idx, o0, o1);
    uint32_t bits = o0 ^ o1;
    float f = __uint_as_float((bits >> 9) | 0x3F800000u) - 1.0f;  // [0,1)
    const float LO = -0.99999994f;                                // nextafter(-1,0)
    float u = fmaf(f, 2.0f, LO);
    u = fmaxf(u, LO);
    return 1.41421356f * erfinvf(u);
}

__device__ __forceinline__ float fast_tanh(float x) {
    float y;
    asm("tanh.approx.f32 %0, %1;" : "=f"(y) : "f"(x));
    return y;
}

__device__ __forceinline__ float breduce_sum(float v, volatile float* red) {
    int tid = threadIdx.x, lane = tid & 31, wrp = tid >> 5;
#pragma unroll
    for (int o = 16; o; o >>= 1) v += __shfl_down_sync(0xffffffffu, v, o);
    if (lane == 0) red[wrp] = v;
    __syncthreads();
    float r = (red[0] + red[1]) + (red[2] + red[3]);
    __syncthreads();
    return r;
}

__device__ __forceinline__ float breduce_max(float v, volatile float* red) {
    int tid = threadIdx.x, lane = tid & 31, wrp = tid >> 5;
#pragma unroll
    for (int o = 16; o; o >>= 1) v = fmaxf(v, __shfl_down_sync(0xffffffffu, v, o));
    if (lane == 0) red[wrp] = v;
    __syncthreads();
    float r = fmaxf(fmaxf(red[0], red[1]), fmaxf(red[2], red[3]));
    __syncthreads();
    return r;
}

// 3-value block sum in one sync round
__device__ __forceinline__ void breduce_sum3(float& a, float& b, float& c,
                                             volatile float* red12) {
    int tid = threadIdx.x, lane = tid & 31, wrp = tid >> 5;
#pragma unroll
    for (int o = 16; o; o >>= 1) {
        a += __shfl_down_sync(0xffffffffu, a, o);
        b += __shfl_down_sync(0xffffffffu, b, o);
        c += __shfl_down_sync(0xffffffffu, c, o);
    }
    if (lane == 0) {
        red12[wrp * 3 + 0] = a;
        red12[wrp * 3 + 1] = b;
        red12[wrp * 3 + 2] = c;
    }
    __syncthreads();
    a = (red12[0] + red12[3]) + (red12[6] + red12[9]);
    b = (red12[1] + red12[4]) + (red12[7] + red12[10]);
    c = (red12[2] + red12[5]) + (red12[8] + red12[11]);
    __syncthreads();
}

// ------------------------------------------- Kernel 0: item_emb -> bf16 table
__global__ __launch_bounds__(256) void conv_item_kernel(const float* __restrict__ item_emb) {
    const int total = (NITEMS + 1) * (Dd / 4);          // float4 count
    for (int i = blockIdx.x * 256 + threadIdx.x; i < total; i += gridDim.x * 256) {
        float4 v = ((const float4*)item_emb)[i];
        __nv_bfloat162 lo = __floats2bfloat162_rn(v.x, v.y);
        __nv_bfloat162 hi = __floats2bfloat162_rn(v.z, v.w);
        uint2 p;
        p.x = *(uint32_t*)&lo;
        p.y = *(uint32_t*)&hi;
        ((uint2*)g_Ih)[i] = p;
    }
}

// ------------------------------------------- Kernel E: precompute lognormal factors
__global__ __launch_bounds__(256) void eps_kernel() {
    int idx = blockIdx.x * 256 + threadIdx.x;
    if (idx < Bb * Ll) {
        float e1 = jax_normal(1u, (uint32_t)idx);
        float e2 = jax_normal(2u, (uint32_t)idx);
        g_F1[idx] = expf(0.1f * e1);
        g_F2[idx] = expf(0.1f * e2);
    }
}

// =================================================================
// bf16 m16n8k16 MMA; smem tiles: uint32 k-pairs, row stride PADU uint32
// =================================================================
#define PADU 68

// ------------------------------------------- Kernel A: KW = item_emb @ Wk (bf16 MMA)
#define KW_GRID 148
#define KW_TILES ((NITEMS + 1 + 127) / 128)   // 782

__global__ __launch_bounds__(256, 2) void kw_kernel(const float* __restrict__ Wk) {
    extern __shared__ uint32_t smem_u[];
    uint32_t* sW  = smem_u;                    // [128 n][68]
    uint32_t* sA0 = smem_u + 128 * PADU;
    uint32_t* sA1 = sA0 + 128 * PADU;

    const int tid  = threadIdx.x;
    const int lane = tid & 31;
    const int wid  = tid >> 5;
    const int gid  = lane >> 2;      // 0..7
    const int tig  = lane & 3;       // 0..3
    const int stripe = (wid & 3) * 32;
    const int colh   = (wid >> 2) * 64;

    // sW[n][p] = {bf16(Wk[2p][n]), bf16(Wk[2p+1][n])} — coalesced fill
#pragma unroll 8
    for (int i = tid; i < 64 * 128; i += 256) {
        int p = i >> 7, n = i & 127;
        float a = Wk[(2 * p) * Dd + n];
        float b = Wk[(2 * p + 1) * Dd + n];
        __nv_bfloat162 h = __floats2bfloat162_rn(a, b);
        sW[n * PADU + p] = *(uint32_t*)&h;
    }

    uint32_t* bufs[2] = { sA0, sA1 };
    int cur = 0;
    int t = blockIdx.x;

#define LOAD_TILE(dst, tt) do {                                               \
        const int row0_ = (tt) * 128;                                         \
        for (int i = tid; i < 128 * 16; i += 256) {                           \
            int r_ = i >> 4, c_ = i & 15;                                     \
            int sr_ = row0_ + r_; if (sr_ > NITEMS) sr_ = NITEMS;             \
            const char* src_ = (const char*)g_Ih + (size_t)sr_ * 256 + c_ * 16;\
            uint32_t d_ = (uint32_t)__cvta_generic_to_shared(                 \
                              (dst) + r_ * PADU + c_ * 4);                    \
            asm volatile("cp.async.ca.shared.global [%0], [%1], 16;\n"        \
                         :: "r"(d_), "l"(src_));                              \
        }                                                                     \
    } while (0)

    if (t < KW_TILES) LOAD_TILE(bufs[0], t);
    asm volatile("cp.async.commit_group;\n");

    while (t < KW_TILES) {
        int tn = t + KW_GRID;
        if (tn < KW_TILES) LOAD_TILE(bufs[cur ^ 1], tn);
        asm volatile("cp.async.commit_group;\n");
        asm volatile("cp.async.wait_group 1;\n");
        __syncthreads();

        uint32_t* sA = bufs[cur];
        float acc[2][8][4];
#pragma unroll
        for (int mi = 0; mi < 2; mi++)
#pragma unroll
            for (int ni = 0; ni < 8; ni++)
#pragma unroll
                for (int j = 0; j < 4; j++) acc[mi][ni][j] = 0.f;

#pragma unroll
        for (int ks = 0; ks < 8; ks++) {
            const int p0 = ks * 8;
            uint32_t a[2][4];
#pragma unroll
            for (int mi = 0; mi < 2; mi++) {
                int r = stripe + mi * 16 + gid;
                a[mi][0] = sA[r * PADU + p0 + tig];
                a[mi][1] = sA[(r + 8) * PADU + p0 + tig];
                a[mi][2] = sA[r * PADU + p0 + tig + 4];
                a[mi][3] = sA[(r + 8) * PADU + p0 + tig + 4];
            }
            uint32_t bf[8][2];
#pragma unroll
            for (int ni = 0; ni < 8; ni++) {
                int n = colh + ni * 8 + gid;
                bf[ni][0] = sW[n * PADU + p0 + tig];
                bf[ni][1] = sW[n * PADU + p0 + tig + 4];
            }
#pragma unroll
            for (int mi = 0; mi < 2; mi++)
#pragma unroll
                for (int ni = 0; ni < 8; ni++) {
                    asm volatile(
                        "mma.sync.aligned.m16n8k16.row.col.f32.bf16.bf16.f32 "
                        "{%0,%1,%2,%3}, {%4,%5,%6,%7}, {%8,%9}, {%0,%1,%2,%3};"
                        : "+f"(acc[mi][ni][0]), "+f"(acc[mi][ni][1]),
                          "+f"(acc[mi][ni][2]), "+f"(acc[mi][ni][3])
                        : "r"(a[mi][0]), "r"(a[mi][1]), "r"(a[mi][2]), "r"(a[mi][3]),
                          "r"(bf[ni][0]), "r"(bf[ni][1]));
                }
        }

        // epilogue: bf16 pack + store
        const int row0 = t * 128;
        uint32_t* kw32 = (uint32_t*)g_KWh;
#pragma unroll
        for (int mi = 0; mi < 2; mi++) {
            int r0 = row0 + stripe + mi * 16 + gid;
            int r1 = r0 + 8;
#pragma unroll
            for (int ni = 0; ni < 8; ni++) {
                int c = colh + ni * 8 + tig * 2;
                if (r0 <= NITEMS) {
                    __nv_bfloat162 h = __floats2bfloat162_rn(acc[mi][ni][0], acc[mi][ni][1]);
                    kw32[(size_t)r0 * (Dd / 2) + (c >> 1)] = *(uint32_t*)&h;
                }
                if (r1 <= NITEMS) {
                    __nv_bfloat162 h = __floats2bfloat162_rn(acc[mi][ni][2], acc[mi][ni][3]);
                    kw32[(size_t)r1 * (Dd / 2) + (c >> 1)] = *(uint32_t*)&h;
                }
            }
        }
        __syncthreads();
        cur ^= 1;
        t = tn;
    }
#undef LOAD_TILE
}

// ------------------------------------------- Kernel B: Q = user_emb[uidx] @ Wq + b_att
__global__ __launch_bounds__(256) void q_kernel(const float* __restrict__ user_emb,
                                                const int* __restrict__ user_idx,
                                                const float* __restrict__ Wq,
                                                const float* __restrict__ b_att) {
    extern __shared__ uint32_t smem_u[];
    uint32_t* sW = smem_u;                 // [128 n][68]
    uint32_t* sA = smem_u + 128 * PADU;    // [32 m][68]

    const int tid  = threadIdx.x;
    const int lane = tid & 31;
    const int wid  = tid >> 5;
    const int gid  = lane >> 2;
    const int tig  = lane & 3;
    const int mrow = (wid & 1) * 16;
    const int ncol = (wid >> 1) * 32;
    const int row0 = blockIdx.x * 32;

#pragma unroll 8
    for (int i = tid; i < 64 * 128; i += 256) {
        int p = i >> 7, n = i & 127;
        float a = Wq[(2 * p) * Dd + n];
        float b = Wq[(2 * p + 1) * Dd + n];
        __nv_bfloat162 h = __floats2bfloat162_rn(a, b);
        sW[n * PADU + p] = *(uint32_t*)&h;
    }
#pragma unroll
    for (int i = tid; i < 32 * 64; i += 256) {
        int r = i >> 6, p = i & 63;
        int u = user_idx[row0 + r];
        float2 v = *(const float2*)(user_emb + (size_t)u * Dd + 2 * p);
        __nv_bfloat162 h = __floats2bfloat162_rn(v.x, v.y);
        sA[r * PADU + p] = *(uint32_t*)&h;
    }
    __syncthreads();

    float acc[4][4];
#pragma unroll
    for (int ni = 0; ni < 4; ni++)
#pragma unroll
        for (int j = 0; j < 4; j++) acc[ni][j] = 0.f;

#pragma unroll
    for (int ks = 0; ks < 8; ks++) {
        const int p0 = ks * 8;
        uint32_t a[4];
        a[0] = sA[(mrow + gid) * PADU + p0 + tig];
        a[1] = sA[(mrow + 8 + gid) * PADU + p0 + tig];
        a[2] = sA[(mrow + gid) * PADU + p0 + tig + 4];
        a[3] = sA[(mrow + 8 + gid) * PADU + p0 + tig + 4];
        uint32_t bf[4][2];
#pragma unroll
        for (int ni = 0; ni < 4; ni++) {
            int n = ncol + ni * 8 + gid;
            bf[ni][0] = sW[n * PADU + p0 + tig];
            bf[ni][1] = sW[n * PADU + p0 + tig + 4];
        }
#pragma unroll
        for (int ni = 0; ni < 4; ni++) {
            asm volatile(
                "mma.sync.aligned.m16n8k16.row.col.f32.bf16.bf16.f32 "
                "{%0,%1,%2,%3}, {%4,%5,%6,%7}, {%8,%9}, {%0,%1,%2,%3};"
                : "+f"(acc[ni][0]), "+f"(acc[ni][1]),
                  "+f"(acc[ni][2]), "+f"(acc[ni][3])
                : "r"(a[0]), "r"(a[1]), "r"(a[2]), "r"(a[3]),
                  "r"(bf[ni][0]), "r"(bf[ni][1]));
        }
    }

    {
        int r0 = row0 + mrow + gid;
        int r1 = r0 + 8;
#pragma unroll
        for (int ni = 0; ni < 4; ni++) {
            int c = ncol + ni * 8 + tig * 2;
            float2 ba = *(const float2*)(b_att + c);
            *(float2*)(g_Q + (size_t)r0 * Dd + c) =
                make_float2(acc[ni][0] + ba.x, acc[ni][1] + ba.y);
            *(float2*)(g_Q + (size_t)r1 * Dd + c) =
                make_float2(acc[ni][2] + ba.x, acc[ni][3] + ba.y);
        }
    }
}

// ------------------------------------------- Kernel C: fused BAM forward
__global__ __launch_bounds__(128, 8) void fused_kernel(
    const float* __restrict__ user_emb,
    const float* __restrict__ item_emb,
    const float* __restrict__ v_att,
    const float* __restrict__ ln_u_g, const float* __restrict__ ln_u_b,
    const float* __restrict__ ln_i_g, const float* __restrict__ ln_i_b,
    const float* __restrict__ pred_W, const float* __restrict__ pred_b,
    const int* __restrict__ user_hist,
    const int* __restrict__ user_idx,
    const int* __restrict__ item_idx,
    float* __restrict__ out)
{
    __shared__ __align__(16) float sh_q[Dd];
    __shared__ __align__(16) float sh_u[Dd];
    __shared__ __align__(16) float sh_v[Dd];
    __shared__ int   sh_r[Ll];
    __shared__ float sh_s[Ll];
    __shared__ float sh_w1[Ll];
    __shared__ float sh_w2[Ll];
    __shared__ float red[12];
    __shared__ __align__(16) float sred[2][4][Dd];   // cross-warp ctx partials

    const int tid  = threadIdx.x;
    const int lane = tid & 31;
    const int wrp  = tid >> 5;
    const int b    = blockIdx.x;
    const int uidx = user_idx[b];
    const int tgt  = item_idx[b];

    sh_u[tid] = user_emb[(size_t)uidx * Dd + tid];
    sh_q[tid] = g_Q[(size_t)b * Dd + tid];     // includes b_att
    sh_v[tid] = v_att[tid];
    float validf = 0.f;
    for (int l = tid; l < Ll; l += 128) {
        int r = user_hist[(size_t)uidx * Ll + l];
        bool ok = (r != tgt) && (r != NITEMS);
        sh_r[l] = ok ? r : -1;
        validf += ok ? 1.f : 0.f;
    }
    __syncthreads();

    float nvf = breduce_sum(validf, red);
    int n_valid = (int)(nvf + 0.5f);
    float nv_clamped = (n_valid > 0) ? (float)n_valid : 1.0f;
    float mu_p = -logf(nv_clamped);

    // scores: warp per l, 2 rows per iteration; lane covers 4 dims (8B bf16)
    float4 q4, v4;
    {
        float2 qa = *(const float2*)(sh_q + lane * 4);
        float2 qb = *(const float2*)(sh_q + lane * 4 + 2);
        q4 = make_float4(qa.x, qa.y, qb.x, qb.y);
        float2 va = *(const float2*)(sh_v + lane * 4);
        float2 vb = *(const float2*)(sh_v + lane * 4 + 2);
        v4 = make_float4(va.x, va.y, vb.x, vb.y);
    }
    for (int l = wrp; l < Ll; l += 8) {
        int l1 = l + 4;
        int r0 = sh_r[l];
        int r1 = (l1 < Ll) ? sh_r[l1] : -1;
        uint2 raw0 = make_uint2(0u, 0u), raw1 = make_uint2(0u, 0u);
        if (r0 >= 0)
            raw0 = ((const uint2*)(g_KWh + (size_t)r0 * Dd))[lane];
        if (r1 >= 0)
            raw1 = ((const uint2*)(g_KWh + (size_t)r1 * Dd))[lane];

#pragma unroll
        for (int j = 0; j < 2; j++) {
            int rr = j ? r1 : r0;
            int ll = j ? l1 : l;
            if (ll >= Ll) break;
            float sval = -1e30f;
            if (rr >= 0) {
                uint2 raw = j ? raw1 : raw0;
                float2 f0 = __bfloat1622float2(*(__nv_bfloat162*)&raw.x);
                float2 f1 = __bfloat1622float2(*(__nv_bfloat162*)&raw.y);
                float tv = v4.x * fast_tanh(q4.x + f0.x);
                tv = fmaf(v4.y, fast_tanh(q4.y + f0.y), tv);
                tv = fmaf(v4.z, fast_tanh(q4.z + f1.x), tv);
                tv = fmaf(v4.w, fast_tanh(q4.w + f1.y), tv);
#pragma unroll
                for (int o = 16; o; o >>= 1)
                    tv += __shfl_down_sync(0xffffffffu, tv, o);
                sval = tv * 0.25f;   // / TAU
            }
            if (lane == 0) sh_s[ll] = sval;
        }
    }
    __syncthreads();

    // softmax
    float m = -1e30f;
    for (int l = tid; l < Ll; l += 128) m = fmaxf(m, sh_s[l]);
    m = breduce_max(m, red);

    float esum = 0.f;
    for (int l = tid; l < Ll; l += 128) {
        float e = 0.f;
        if (sh_r[l] >= 0) e = expf(sh_s[l] - m);
        sh_s[l] = e;
        esum += e;
    }
    esum = breduce_sum(esum, red);
    float inv_es = (esum > 0.f) ? (1.0f / esum) : 0.f;

    // sampled weights via precomputed lognormal factors + KL; triple reduce
    float klacc = 0.f, s1 = 0.f, s2 = 0.f;
    for (int l = tid; l < Ll; l += 128) {
        float w1 = 0.f, w2 = 0.f;
        if (sh_r[l] >= 0) {
            float alpha = sh_s[l] * inv_es;
            float ap = alpha + 1e-24f;
            float mu = logf(ap);
            int idx = b * Ll + l;
            w1 = ap * g_F1[idx];
            w2 = ap * g_F2[idx];
            float dmu = mu - mu_p;
            klacc += 1.8075851f + 0.5f * dmu * dmu;  // log(10)-0.5+SIG_Q^2/2 + d^2/2
        }
        sh_w1[l] = w1;
        sh_w2[l] = w2;
        s1 += w1;
        s2 += w2;
    }
    breduce_sum3(klacc, s1, s2, red);
    if (tid == 0) { g_klp[b] = klacc; g_cnt[b] = n_valid; }
    float i1 = 1.0f / (s1 + 1e-12f);
    float i2 = 1.0f / (s2 + 1e-12f);

    // contexts: warp-per-row gather with LDG.128 (value path stays fp32).
    // Warp w owns rows [w*50, w*50+50); lane loads dims [lane*4, lane*4+4)
    // as one float4 per row. 2 rows in flight. Cross-warp reduce via smem.
    {
        float4 cu4 = make_float4(0.f, 0.f, 0.f, 0.f);
        float4 ci4 = make_float4(0.f, 0.f, 0.f, 0.f);
        const int lbase = wrp * 50;
#pragma unroll 5
        for (int j = 0; j < 50; j += 2) {
            int l0 = lbase + j, l1 = l0 + 1;
            int r0 = sh_r[l0], r1 = sh_r[l1];
            float4 v0 = make_float4(0.f, 0.f, 0.f, 0.f);
            float4 v1 = make_float4(0.f, 0.f, 0.f, 0.f);
            if (r0 >= 0) v0 = ((const float4*)(item_emb + (size_t)r0 * Dd))[lane];
            if (r1 >= 0) v1 = ((const float4*)(item_emb + (size_t)r1 * Dd))[lane];
            float w10 = sh_w1[l0], w20 = sh_w2[l0];
            float w11 = sh_w1[l1], w21 = sh_w2[l1];
            cu4.x = fmaf(w10, v0.x, fmaf(w11, v1.x, cu4.x));
            cu4.y = fmaf(w10, v0.y, fmaf(w11, v1.y, cu4.y));
            cu4.z = fmaf(w10, v0.z, fmaf(w11, v1.z, cu4.z));
            cu4.w = fmaf(w10, v0.w, fmaf(w11, v1.w, cu4.w));
            ci4.x = fmaf(w20, v0.x, fmaf(w21, v1.x, ci4.x));
            ci4.y = fmaf(w20, v0.y, fmaf(w21, v1.y, ci4.y));
            ci4.z = fmaf(w20, v0.z, fmaf(w21, v1.z, ci4.z));
            ci4.w = fmaf(w20, v0.w, fmaf(w21, v1.w, ci4.w));
        }
        *(float4*)&sred[0][wrp][lane * 4] = cu4;
        *(float4*)&sred[1][wrp][lane * 4] = ci4;
    }
    __syncthreads();
    float cu = (sred[0][0][tid] + sred[0][1][tid]) +
               (sred[0][2][tid] + sred[0][3][tid]);
    float ci = (sred[1][0][tid] + sred[1][1][tid]) +
               (sred[1][2][tid] + sred[1][3][tid]);
    cu *= i1; ci *= i2;

    // layernorm(u ctx * user_emb)
    float xu = cu * sh_u[tid];
    float mean_u = breduce_sum(xu, red) * (1.0f / Dd);
    float du = xu - mean_u;
    float var_u = breduce_sum(du * du, red) * (1.0f / Dd);
    float us = du * rsqrtf(var_u + 1e-5f) * ln_u_g[tid] + ln_u_b[tid];

    // layernorm(i ctx * item_emb[target])
    float xi = ci * item_emb[(size_t)tgt * Dd + tid];
    float mean_i = breduce_sum(xi, red) * (1.0f / Dd);
    float di = xi - mean_i;
    float var_i = breduce_sum(di * di, red) * (1.0f / Dd);
    float is_ = di * rsqrtf(var_i + 1e-5f) * ln_i_g[tid] + ln_i_b[tid];

    float pv = us * is_ * pred_W[tid];
    float dot = breduce_sum(pv, red);
    if (tid == 0) out[b] = dot + pred_b[0];
}

// ------------------------------------------- Kernel D: deterministic KL reduce
__global__ __launch_bounds__(256) void kl_reduce_kernel(float* __restrict__ out,
                                                        int out_size) {
    __shared__ float rs[8];
    __shared__ int   ri[8];
    int tid = threadIdx.x;
    float s = 0.f; int c = 0;
    for (int i = tid; i < Bb; i += 256) { s += g_klp[i]; c += g_cnt[i]; }
#pragma unroll
    for (int o = 16; o; o >>= 1) {
        s += __shfl_down_sync(0xffffffffu, s, o);
        c += __shfl_down_sync(0xffffffffu, c, o);
    }
    if ((tid & 31) == 0) { rs[tid >> 5] = s; ri[tid >> 5] = c; }
    __syncthreads();
    if (tid == 0) {
        float S = 0.f; int C = 0;
        for (int i = 0; i < 8; i++) { S += rs[i]; C += ri[i]; }
        if (C < 1) C = 1;
        float kl = 0.25f * S / (float)C;   // BETA * sum / cnt ; (kl_u+kl_i)/2 == kl_u
        if (out_size > Bb) out[Bb] = kl;
    }
}

// ------------------------------------------- launcher
extern "C" void kernel_launch(void* const* d_in, const int* in_sizes, int n_in,
                              void* d_out, int out_size) {
    const float* user_emb = (const float*)d_in[0];
    const float* item_emb = (const float*)d_in[1];
    const float* Wq       = (const float*)d_in[2];
    const float* Wk       = (const float*)d_in[3];
    const float* b_att    = (const float*)d_in[4];
    const float* v_att    = (const float*)d_in[5];
    const float* ln_u_g   = (const float*)d_in[6];
    const float* ln_u_b   = (const float*)d_in[7];
    const float* ln_i_g   = (const float*)d_in[8];
    const float* ln_i_b   = (const float*)d_in[9];
    const float* pred_W   = (const float*)d_in[10];
    const float* pred_b   = (const float*)d_in[11];
    const int* user_hist  = (const int*)d_in[12];
    const int* user_idx   = (const int*)d_in[13];
    const int* item_idx   = (const int*)d_in[14];
    float* out = (float*)d_out;

    static cudaStream_t s1 = nullptr, s2 = nullptr;
    static cudaEvent_t evRoot = nullptr, ev1 = nullptr, ev2 = nullptr;
    if (s1 == nullptr) {
        cudaStreamCreateWithFlags(&s1, cudaStreamNonBlocking);
        cudaStreamCreateWithFlags(&s2, cudaStreamNonBlocking);
        cudaEventCreateWithFlags(&evRoot, cudaEventDisableTiming);
        cudaEventCreateWithFlags(&ev1, cudaEventDisableTiming);
        cudaEventCreateWithFlags(&ev2, cudaEventDisableTiming);
    }

    const int kw_smem = 3 * 128 * PADU * 4;          // 104448 B
    const int q_smem  = (128 + 32) * PADU * 4;       // 43520 B
    cudaFuncSetAttribute(kw_kernel, cudaFuncAttributeMaxDynamicSharedMemorySize,
                         kw_smem);
    cudaFuncSetAttribute(q_kernel, cudaFuncAttributeMaxDynamicSharedMemorySize,
                         q_smem);

    // fork: eps on s1, q on s2, conv+kw on main stream
    cudaEventRecord(evRoot, 0);
    cudaStreamWaitEvent(s1, evRoot, 0);
    cudaStreamWaitEvent(s2, evRoot, 0);

    eps_kernel<<<(Bb * Ll + 255) / 256, 256, 0, s1>>>();
    q_kernel<<<Bb / 32, 256, q_smem, s2>>>(user_emb, user_idx, Wq, b_att);

    conv_item_kernel<<<1184, 256>>>(item_emb);
    kw_kernel<<<KW_GRID, 256, kw_smem>>>(Wk);

    // join
    cudaEventRecord(ev1, s1);
    cudaEventRecord(ev2, s2);
    cudaStreamWaitEvent(0, ev1, 0);
    cudaStreamWaitEvent(0, ev2, 0);

    fused_kernel<<<Bb, 128>>>(user_emb, item_emb, v_att,
                              ln_u_g, ln_u_b, ln_i_g, ln_i_b,
                              pred_W, pred_b, user_hist, user_idx, item_idx, out);
    kl_reduce_kernel<<<1, 256>>>(out, out_size);
}

// round 12
// speedup vs baseline: 1.6561x; 1.1069x over previous
#include <cuda_runtime.h>
#include <cuda_bf16.h>
#include <stdint.h>

#define Dd 128
#define Ll 200
#define Bb 4096
#define NITEMS 100000

// Scratch (static device globals: allocation-free per harness rules)
__device__ __nv_bfloat16 g_KWh[(NITEMS + 1) * Dd];  // item_emb @ Wk (bf16)
__device__ __nv_bfloat16 g_Ih[(NITEMS + 1) * Dd];   // item_emb in bf16 (GEMM input only)
__device__ float g_Q[Bb * Dd];                      // Q = u@Wq + b_att (fp32)
__device__ float g_F1[Bb * Ll];                     // exp(0.1*eps1)
__device__ float g_F2[Bb * Ll];                     // exp(0.1*eps2)
__device__ float g_klp[Bb];
__device__ int   g_cnt[Bb];

// ---------------------------------------------------------------- utilities

__device__ __forceinline__ uint32_t rotl32(uint32_t x, int d) {
    return (x << d) | (x >> (32 - d));
}

// Exact JAX threefry2x32 (20 rounds)
__device__ __forceinline__ void threefry2x32(uint32_t k0, uint32_t k1,
                                             uint32_t c0, uint32_t c1,
                                             uint32_t& o0, uint32_t& o1) {
    uint32_t ks2 = k0 ^ k1 ^ 0x1BD11BDAu;
    uint32_t x0 = c0 + k0, x1 = c1 + k1;
#define TF_R(r) { x0 += x1; x1 = rotl32(x1, r); x1 ^= x0; }
    TF_R(13) TF_R(15) TF_R(26) TF_R(6)  x0 += k1;  x1 += ks2 + 1u;
    TF_R(17) TF_R(29) TF_R(16) TF_R(24) x0 += ks2; x1 += k0 + 2u;
    TF_R(13) TF_R(15) TF_R(26) TF_R(6)  x0 += k0;  x1 += k1 + 3u;
    TF_R(17) TF_R(29) TF_R(16) TF_R(24) x0 += k1;  x1 += ks2 + 4u;
    TF_R(13) TF_R(15) TF_R(26) TF_R(6)  x0 += ks2; x1 += k0 + 5u;
#undef TF_R
    o0 = x0; o1 = x1;
}

// jax.random.normal under jax_threefry_partitionable=True
__device__ __forceinline__ float jax_normal(uint32_t k1, uint32_t idx) {
    uint32_t o0, o1;
    threefry2x32(0u, k1, 0u, idx, o0, o1);
    uint32_t bits = o0 ^ o1;
    float f = __uint_as_float((bits >> 9) | 0x3F800000u) - 1.0f;  // [0,1)
    const float LO = -0.99999994f;                                // nextafter(-1,0)
    float u = fmaf(f, 2.0f, LO);
    u = fmaxf(u, LO);
    return 1.41421356f * erfinvf(u);
}

__device__ __forceinline__ float fast_tanh(float x) {
    float y;
    asm("tanh.approx.f32 %0, %1;" : "=f"(y) : "f"(x));
    return y;
}

__device__ __forceinline__ float breduce_sum(float v, volatile float* red) {
    int tid = threadIdx.x, lane = tid & 31, wrp = tid >> 5;
#pragma unroll
    for (int o = 16; o; o >>= 1) v += __shfl_down_sync(0xffffffffu, v, o);
    if (lane == 0) red[wrp] = v;
    __syncthreads();
    float r = (red[0] + red[1]) + (red[2] + red[3]);
    __syncthreads();
    return r;
}

__device__ __forceinline__ float breduce_max(float v, volatile float* red) {
    int tid = threadIdx.x, lane = tid & 31, wrp = tid >> 5;
#pragma unroll
    for (int o = 16; o; o >>= 1) v = fmaxf(v, __shfl_down_sync(0xffffffffu, v, o));
    if (lane == 0) red[wrp] = v;
    __syncthreads();
    float r = fmaxf(fmaxf(red[0], red[1]), fmaxf(red[2], red[3]));
    __syncthreads();
    return r;
}

// 3-value block sum in one sync round
__device__ __forceinline__ void breduce_sum3(float& a, float& b, float& c,
                                             volatile float* red12) {
    int tid = threadIdx.x, lane = tid & 31, wrp = tid >> 5;
#pragma unroll
    for (int o = 16; o; o >>= 1) {
        a += __shfl_down_sync(0xffffffffu, a, o);
        b += __shfl_down_sync(0xffffffffu, b, o);
        c += __shfl_down_sync(0xffffffffu, c, o);
    }
    if (lane == 0) {
        red12[wrp * 3 + 0] = a;
        red12[wrp * 3 + 1] = b;
        red12[wrp * 3 + 2] = c;
    }
    __syncthreads();
    a = (red12[0] + red12[3]) + (red12[6] + red12[9]);
    b = (red12[1] + red12[4]) + (red12[7] + red12[10]);
    c = (red12[2] + red12[5]) + (red12[8] + red12[11]);
    __syncthreads();
}

// 4-value block sum in one sync round
__device__ __forceinline__ void breduce_sum4(float& a, float& b, float& c, float& d,
                                             volatile float* red16) {
    int tid = threadIdx.x, lane = tid & 31, wrp = tid >> 5;
#pragma unroll
    for (int o = 16; o; o >>= 1) {
        a += __shfl_down_sync(0xffffffffu, a, o);
        b += __shfl_down_sync(0xffffffffu, b, o);
        c += __shfl_down_sync(0xffffffffu, c, o);
        d += __shfl_down_sync(0xffffffffu, d, o);
    }
    if (lane == 0) {
        red16[wrp * 4 + 0] = a;
        red16[wrp * 4 + 1] = b;
        red16[wrp * 4 + 2] = c;
        red16[wrp * 4 + 3] = d;
    }
    __syncthreads();
    a = (red16[0] + red16[4]) + (red16[8] + red16[12]);
    b = (red16[1] + red16[5]) + (red16[9] + red16[13]);
    c = (red16[2] + red16[6]) + (red16[10] + red16[14]);
    d = (red16[3] + red16[7]) + (red16[11] + red16[15]);
    __syncthreads();
}

// ------------------------------------------- Kernel 0: item_emb -> bf16 table
__global__ __launch_bounds__(256) void conv_item_kernel(const float* __restrict__ item_emb) {
    const int total = (NITEMS + 1) * (Dd / 4);          // float4 count
    for (int i = blockIdx.x * 256 + threadIdx.x; i < total; i += gridDim.x * 256) {
        float4 v = ((const float4*)item_emb)[i];
        __nv_bfloat162 lo = __floats2bfloat162_rn(v.x, v.y);
        __nv_bfloat162 hi = __floats2bfloat162_rn(v.z, v.w);
        uint2 p;
        p.x = *(uint32_t*)&lo;
        p.y = *(uint32_t*)&hi;
        ((uint2*)g_Ih)[i] = p;
    }
}

// ------------------------------------------- Kernel E: precompute lognormal factors
__global__ __launch_bounds__(256) void eps_kernel() {
    int idx = blockIdx.x * 256 + threadIdx.x;
    if (idx < Bb * Ll) {
        float e1 = jax_normal(1u, (uint32_t)idx);
        float e2 = jax_normal(2u, (uint32_t)idx);
        g_F1[idx] = expf(0.1f * e1);
        g_F2[idx] = expf(0.1f * e2);
    }
}

// =================================================================
// bf16 m16n8k16 MMA; smem tiles: uint32 k-pairs, row stride PADU uint32
// =================================================================
#define PADU 68

// ------------------------------------------- Kernel A: KW = item_emb @ Wk (bf16 MMA)
// 64-row tiles, 3 blocks/SM (smem 70KB, regs <=83). 8 warps: warp (wid&3)
// owns m-quarter of 16 rows, (wid>>2) owns 64-col half. Double-buffered cp.async.
#define KW_GRID 148
#define KW_TILES ((NITEMS + 1 + 63) / 64)   // 1563

__global__ __launch_bounds__(256, 3) void kw_kernel(const float* __restrict__ Wk) {
    extern __shared__ uint32_t smem_u[];
    uint32_t* sW  = smem_u;                    // [128 n][68]
    uint32_t* sA0 = smem_u + 128 * PADU;       // [64 m][68]
    uint32_t* sA1 = sA0 + 64 * PADU;

    const int tid  = threadIdx.x;
    const int lane = tid & 31;
    const int wid  = tid >> 5;
    const int gid  = lane >> 2;      // 0..7
    const int tig  = lane & 3;       // 0..3
    const int stripe = (wid & 3) * 16;
    const int colh   = (wid >> 2) * 64;

    // sW[n][p] = {bf16(Wk[2p][n]), bf16(Wk[2p+1][n])} — coalesced fill
#pragma unroll 8
    for (int i = tid; i < 64 * 128; i += 256) {
        int p = i >> 7, n = i & 127;
        float a = Wk[(2 * p) * Dd + n];
        float b = Wk[(2 * p + 1) * Dd + n];
        __nv_bfloat162 h = __floats2bfloat162_rn(a, b);
        sW[n * PADU + p] = *(uint32_t*)&h;
    }

    uint32_t* bufs[2] = { sA0, sA1 };
    int cur = 0;
    int t = blockIdx.x;

    // async tile loader: 64 rows x 16 16B-chunks (bf16 rows = 256B)
#define LOAD_TILE(dst, tt) do {                                               \
        const int row0_ = (tt) * 64;                                          \
        for (int i = tid; i < 64 * 16; i += 256) {                            \
            int r_ = i >> 4, c_ = i & 15;                                     \
            int sr_ = row0_ + r_; if (sr_ > NITEMS) sr_ = NITEMS;             \
            const char* src_ = (const char*)g_Ih + (size_t)sr_ * 256 + c_ * 16;\
            uint32_t d_ = (uint32_t)__cvta_generic_to_shared(                 \
                              (dst) + r_ * PADU + c_ * 4);                    \
            asm volatile("cp.async.ca.shared.global [%0], [%1], 16;\n"        \
                         :: "r"(d_), "l"(src_));                              \
        }                                                                     \
    } while (0)

    if (t < KW_TILES) LOAD_TILE(bufs[0], t);
    asm volatile("cp.async.commit_group;\n");

    while (t < KW_TILES) {
        int tn = t + KW_GRID;
        if (tn < KW_TILES) LOAD_TILE(bufs[cur ^ 1], tn);
        asm volatile("cp.async.commit_group;\n");
        asm volatile("cp.async.wait_group 1;\n");
        __syncthreads();

        uint32_t* sA = bufs[cur];
        float acc[8][4];
#pragma unroll
        for (int ni = 0; ni < 8; ni++)
#pragma unroll
            for (int j = 0; j < 4; j++) acc[ni][j] = 0.f;

#pragma unroll
        for (int ks = 0; ks < 8; ks++) {
            const int p0 = ks * 8;
            uint32_t a[4];
            {
                int r = stripe + gid;
                a[0] = sA[r * PADU + p0 + tig];
                a[1] = sA[(r + 8) * PADU + p0 + tig];
                a[2] = sA[r * PADU + p0 + tig + 4];
                a[3] = sA[(r + 8) * PADU + p0 + tig + 4];
            }
            uint32_t bf[8][2];
#pragma unroll
            for (int ni = 0; ni < 8; ni++) {
                int n = colh + ni * 8 + gid;
                bf[ni][0] = sW[n * PADU + p0 + tig];
                bf[ni][1] = sW[n * PADU + p0 + tig + 4];
            }
#pragma unroll
            for (int ni = 0; ni < 8; ni++) {
                asm volatile(
                    "mma.sync.aligned.m16n8k16.row.col.f32.bf16.bf16.f32 "
                    "{%0,%1,%2,%3}, {%4,%5,%6,%7}, {%8,%9}, {%0,%1,%2,%3};"
                    : "+f"(acc[ni][0]), "+f"(acc[ni][1]),
                      "+f"(acc[ni][2]), "+f"(acc[ni][3])
                    : "r"(a[0]), "r"(a[1]), "r"(a[2]), "r"(a[3]),
                      "r"(bf[ni][0]), "r"(bf[ni][1]));
            }
        }

        // epilogue: bf16 pack + store
        const int row0 = t * 64;
        uint32_t* kw32 = (uint32_t*)g_KWh;
        {
            int r0 = row0 + stripe + gid;
            int r1 = r0 + 8;
#pragma unroll
            for (int ni = 0; ni < 8; ni++) {
                int c = colh + ni * 8 + tig * 2;
                if (r0 <= NITEMS) {
                    __nv_bfloat162 h = __floats2bfloat162_rn(acc[ni][0], acc[ni][1]);
                    kw32[(size_t)r0 * (Dd / 2) + (c >> 1)] = *(uint32_t*)&h;
                }
                if (r1 <= NITEMS) {
                    __nv_bfloat162 h = __floats2bfloat162_rn(acc[ni][2], acc[ni][3]);
                    kw32[(size_t)r1 * (Dd / 2) + (c >> 1)] = *(uint32_t*)&h;
                }
            }
        }
        __syncthreads();
        cur ^= 1;
        t = tn;
    }
#undef LOAD_TILE
}

// ------------------------------------------- Kernel B: Q = user_emb[uidx] @ Wq + b_att
__global__ __launch_bounds__(256) void q_kernel(const float* __restrict__ user_emb,
                                                const int* __restrict__ user_idx,
                                                const float* __restrict__ Wq,
                                                const float* __restrict__ b_att) {
    extern __shared__ uint32_t smem_u[];
    uint32_t* sW = smem_u;                 // [128 n][68]
    uint32_t* sA = smem_u + 128 * PADU;    // [32 m][68]

    const int tid  = threadIdx.x;
    const int lane = tid & 31;
    const int wid  = tid >> 5;
    const int gid  = lane >> 2;
    const int tig  = lane & 3;
    const int mrow = (wid & 1) * 16;
    const int ncol = (wid >> 1) * 32;
    const int row0 = blockIdx.x * 32;

#pragma unroll 8
    for (int i = tid; i < 64 * 128; i += 256) {
        int p = i >> 7, n = i & 127;
        float a = Wq[(2 * p) * Dd + n];
        float b = Wq[(2 * p + 1) * Dd + n];
        __nv_bfloat162 h = __floats2bfloat162_rn(a, b);
        sW[n * PADU + p] = *(uint32_t*)&h;
    }
#pragma unroll
    for (int i = tid; i < 32 * 64; i += 256) {
        int r = i >> 6, p = i & 63;
        int u = user_idx[row0 + r];
        float2 v = *(const float2*)(user_emb + (size_t)u * Dd + 2 * p);
        __nv_bfloat162 h = __floats2bfloat162_rn(v.x, v.y);
        sA[r * PADU + p] = *(uint32_t*)&h;
    }
    __syncthreads();

    float acc[4][4];
#pragma unroll
    for (int ni = 0; ni < 4; ni++)
#pragma unroll
        for (int j = 0; j < 4; j++) acc[ni][j] = 0.f;

#pragma unroll
    for (int ks = 0; ks < 8; ks++) {
        const int p0 = ks * 8;
        uint32_t a[4];
        a[0] = sA[(mrow + gid) * PADU + p0 + tig];
        a[1] = sA[(mrow + 8 + gid) * PADU + p0 + tig];
        a[2] = sA[(mrow + gid) * PADU + p0 + tig + 4];
        a[3] = sA[(mrow + 8 + gid) * PADU + p0 + tig + 4];
        uint32_t bf[4][2];
#pragma unroll
        for (int ni = 0; ni < 4; ni++) {
            int n = ncol + ni * 8 + gid;
            bf[ni][0] = sW[n * PADU + p0 + tig];
            bf[ni][1] = sW[n * PADU + p0 + tig + 4];
        }
#pragma unroll
        for (int ni = 0; ni < 4; ni++) {
            asm volatile(
                "mma.sync.aligned.m16n8k16.row.col.f32.bf16.bf16.f32 "
                "{%0,%1,%2,%3}, {%4,%5,%6,%7}, {%8,%9}, {%0,%1,%2,%3};"
                : "+f"(acc[ni][0]), "+f"(acc[ni][1]),
                  "+f"(acc[ni][2]), "+f"(acc[ni][3])
                : "r"(a[0]), "r"(a[1]), "r"(a[2]), "r"(a[3]),
                  "r"(bf[ni][0]), "r"(bf[ni][1]));
        }
    }

    {
        int r0 = row0 + mrow + gid;
        int r1 = r0 + 8;
#pragma unroll
        for (int ni = 0; ni < 4; ni++) {
            int c = ncol + ni * 8 + tig * 2;
            float2 ba = *(const float2*)(b_att + c);
            *(float2*)(g_Q + (size_t)r0 * Dd + c) =
                make_float2(acc[ni][0] + ba.x, acc[ni][1] + ba.y);
            *(float2*)(g_Q + (size_t)r1 * Dd + c) =
                make_float2(acc[ni][2] + ba.x, acc[ni][3] + ba.y);
        }
    }
}

// ------------------------------------------- Kernel C: fused BAM forward
__global__ __launch_bounds__(128, 8) void fused_kernel(
    const float* __restrict__ user_emb,
    const float* __restrict__ item_emb,
    const float* __restrict__ v_att,
    const float* __restrict__ ln_u_g, const float* __restrict__ ln_u_b,
    const float* __restrict__ ln_i_g, const float* __restrict__ ln_i_b,
    const float* __restrict__ pred_W, const float* __restrict__ pred_b,
    const int* __restrict__ user_hist,
    const int* __restrict__ user_idx,
    const int* __restrict__ item_idx,
    float* __restrict__ out)
{
    __shared__ __align__(16) float sh_q[Dd];
    __shared__ __align__(16) float sh_u[Dd];
    __shared__ __align__(16) float sh_v[Dd];
    __shared__ int   sh_r[Ll];
    __shared__ float sh_s[Ll];
    __shared__ float sh_w1[Ll];
    __shared__ float sh_w2[Ll];
    __shared__ float red[16];
    __shared__ __align__(16) float sred[2][4][Dd];   // cross-warp ctx partials

    const int tid  = threadIdx.x;
    const int lane = tid & 31;
    const int wrp  = tid >> 5;
    const int b    = blockIdx.x;
    const int uidx = user_idx[b];
    const int tgt  = item_idx[b];

    sh_u[tid] = user_emb[(size_t)uidx * Dd + tid];
    sh_q[tid] = g_Q[(size_t)b * Dd + tid];     // includes b_att
    sh_v[tid] = v_att[tid];
    float validf = 0.f;
    for (int l = tid; l < Ll; l += 128) {
        int r = user_hist[(size_t)uidx * Ll + l];
        bool ok = (r != tgt) && (r != NITEMS);
        sh_r[l] = ok ? r : -1;
        validf += ok ? 1.f : 0.f;
    }
    __syncthreads();

    float nvf = breduce_sum(validf, red);
    int n_valid = (int)(nvf + 0.5f);
    float nv_clamped = (n_valid > 0) ? (float)n_valid : 1.0f;
    float mu_p = -logf(nv_clamped);

    // scores: warp per l, 4 rows/iteration (4 independent shfl chains overlap);
    // lane covers 4 dims (8B bf16 load per row)
    float4 q4, v4;
    {
        float2 qa = *(const float2*)(sh_q + lane * 4);
        float2 qb = *(const float2*)(sh_q + lane * 4 + 2);
        q4 = make_float4(qa.x, qa.y, qb.x, qb.y);
        float2 va = *(const float2*)(sh_v + lane * 4);
        float2 vb = *(const float2*)(sh_v + lane * 4 + 2);
        v4 = make_float4(va.x, va.y, vb.x, vb.y);
    }
    for (int l = wrp; l < Ll; l += 16) {
        int rs0 = sh_r[l];
        int rs1 = (l + 4  < Ll) ? sh_r[l + 4]  : -1;
        int rs2 = (l + 8  < Ll) ? sh_r[l + 8]  : -1;
        int rs3 = (l + 12 < Ll) ? sh_r[l + 12] : -1;
        uint2 raw0 = make_uint2(0u, 0u), raw1 = make_uint2(0u, 0u);
        uint2 raw2 = make_uint2(0u, 0u), raw3 = make_uint2(0u, 0u);
        if (rs0 >= 0) raw0 = ((const uint2*)(g_KWh + (size_t)rs0 * Dd))[lane];
        if (rs1 >= 0) raw1 = ((const uint2*)(g_KWh + (size_t)rs1 * Dd))[lane];
        if (rs2 >= 0) raw2 = ((const uint2*)(g_KWh + (size_t)rs2 * Dd))[lane];
        if (rs3 >= 0) raw3 = ((const uint2*)(g_KWh + (size_t)rs3 * Dd))[lane];

        float t0 = 0.f, t1 = 0.f, t2 = 0.f, t3 = 0.f;
        {
            float2 f0 = __bfloat1622float2(*(__nv_bfloat162*)&raw0.x);
            float2 f1 = __bfloat1622float2(*(__nv_bfloat162*)&raw0.y);
            t0 = v4.x * fast_tanh(q4.x + f0.x);
            t0 = fmaf(v4.y, fast_tanh(q4.y + f0.y), t0);
            t0 = fmaf(v4.z, fast_tanh(q4.z + f1.x), t0);
            t0 = fmaf(v4.w, fast_tanh(q4.w + f1.y), t0);
        }
        {
            float2 f0 = __bfloat1622float2(*(__nv_bfloat162*)&raw1.x);
            float2 f1 = __bfloat1622float2(*(__nv_bfloat162*)&raw1.y);
            t1 = v4.x * fast_tanh(q4.x + f0.x);
            t1 = fmaf(v4.y, fast_tanh(q4.y + f0.y), t1);
            t1 = fmaf(v4.z, fast_tanh(q4.z + f1.x), t1);
            t1 = fmaf(v4.w, fast_tanh(q4.w + f1.y), t1);
        }
        {
            float2 f0 = __bfloat1622float2(*(__nv_bfloat162*)&raw2.x);
            float2 f1 = __bfloat1622float2(*(__nv_bfloat162*)&raw2.y);
            t2 = v4.x * fast_tanh(q4.x + f0.x);
            t2 = fmaf(v4.y, fast_tanh(q4.y + f0.y), t2);
            t2 = fmaf(v4.z, fast_tanh(q4.z + f1.x), t2);
            t2 = fmaf(v4.w, fast_tanh(q4.w + f1.y), t2);
        }
        {
            float2 f0 = __bfloat1622float2(*(__nv_bfloat162*)&raw3.x);
            float2 f1 = __bfloat1622float2(*(__nv_bfloat162*)&raw3.y);
            t3 = v4.x * fast_tanh(q4.x + f0.x);
            t3 = fmaf(v4.y, fast_tanh(q4.y + f0.y), t3);
            t3 = fmaf(v4.z, fast_tanh(q4.z + f1.x), t3);
            t3 = fmaf(v4.w, fast_tanh(q4.w + f1.y), t3);
        }
        // 4 independent butterfly chains — latency overlaps
#pragma unroll
        for (int o = 16; o; o >>= 1) {
            t0 += __shfl_down_sync(0xffffffffu, t0, o);
            t1 += __shfl_down_sync(0xffffffffu, t1, o);
            t2 += __shfl_down_sync(0xffffffffu, t2, o);
            t3 += __shfl_down_sync(0xffffffffu, t3, o);
        }
        if (lane == 0) {
            sh_s[l] = (rs0 >= 0) ? t0 * 0.25f : -1e30f;
            if (l + 4  < Ll) sh_s[l + 4]  = (rs1 >= 0) ? t1 * 0.25f : -1e30f;
            if (l + 8  < Ll) sh_s[l + 8]  = (rs2 >= 0) ? t2 * 0.25f : -1e30f;
            if (l + 12 < Ll) sh_s[l + 12] = (rs3 >= 0) ? t3 * 0.25f : -1e30f;
        }
    }
    __syncthreads();

    // softmax
    float m = -1e30f;
    for (int l = tid; l < Ll; l += 128) m = fmaxf(m, sh_s[l]);
    m = breduce_max(m, red);

    float esum = 0.f;
    for (int l = tid; l < Ll; l += 128) {
        float e = 0.f;
        if (sh_r[l] >= 0) e = expf(sh_s[l] - m);
        sh_s[l] = e;
        esum += e;
    }
    esum = breduce_sum(esum, red);
    float inv_es = (esum > 0.f) ? (1.0f / esum) : 0.f;

    // sampled weights via precomputed lognormal factors + KL; triple reduce
    float klacc = 0.f, s1 = 0.f, s2 = 0.f;
    for (int l = tid; l < Ll; l += 128) {
        float w1 = 0.f, w2 = 0.f;
        if (sh_r[l] >= 0) {
            float alpha = sh_s[l] * inv_es;
            float ap = alpha + 1e-24f;
            float mu = logf(ap);
            int idx = b * Ll + l;
            w1 = ap * g_F1[idx];
            w2 = ap * g_F2[idx];
            float dmu = mu - mu_p;
            klacc += 1.8075851f + 0.5f * dmu * dmu;  // log(10)-0.5+SIG_Q^2/2 + d^2/2
        }
        sh_w1[l] = w1;
        sh_w2[l] = w2;
        s1 += w1;
        s2 += w2;
    }
    breduce_sum3(klacc, s1, s2, red);
    if (tid == 0) { g_klp[b] = klacc; g_cnt[b] = n_valid; }
    float i1 = 1.0f / (s1 + 1e-12f);
    float i2 = 1.0f / (s2 + 1e-12f);

    // contexts: warp-per-row gather with LDG.128 (value path stays fp32).
    {
        float4 cu4 = make_float4(0.f, 0.f, 0.f, 0.f);
        float4 ci4 = make_float4(0.f, 0.f, 0.f, 0.f);
        const int lbase = wrp * 50;
#pragma unroll 5
        for (int j = 0; j < 50; j += 2) {
            int l0 = lbase + j, l1 = l0 + 1;
            int r0 = sh_r[l0], r1 = sh_r[l1];
            float4 v0 = make_float4(0.f, 0.f, 0.f, 0.f);
            float4 v1 = make_float4(0.f, 0.f, 0.f, 0.f);
            if (r0 >= 0) v0 = ((const float4*)(item_emb + (size_t)r0 * Dd))[lane];
            if (r1 >= 0) v1 = ((const float4*)(item_emb + (size_t)r1 * Dd))[lane];
            float w10 = sh_w1[l0], w20 = sh_w2[l0];
            float w11 = sh_w1[l1], w21 = sh_w2[l1];
            cu4.x = fmaf(w10, v0.x, fmaf(w11, v1.x, cu4.x));
            cu4.y = fmaf(w10, v0.y, fmaf(w11, v1.y, cu4.y));
            cu4.z = fmaf(w10, v0.z, fmaf(w11, v1.z, cu4.z));
            cu4.w = fmaf(w10, v0.w, fmaf(w11, v1.w, cu4.w));
            ci4.x = fmaf(w20, v0.x, fmaf(w21, v1.x, ci4.x));
            ci4.y = fmaf(w20, v0.y, fmaf(w21, v1.y, ci4.y));
            ci4.z = fmaf(w20, v0.z, fmaf(w21, v1.z, ci4.z));
            ci4.w = fmaf(w20, v0.w, fmaf(w21, v1.w, ci4.w));
        }
        *(float4*)&sred[0][wrp][lane * 4] = cu4;
        *(float4*)&sred[1][wrp][lane * 4] = ci4;
    }
    __syncthreads();
    float cu = (sred[0][0][tid] + sred[0][1][tid]) +
               (sred[0][2][tid] + sred[0][3][tid]);
    float ci = (sred[1][0][tid] + sred[1][1][tid]) +
               (sred[1][2][tid] + sred[1][3][tid]);
    cu *= i1; ci *= i2;

    // both layernorms via sum/sumsq, single 4-value reduce round
    float xu = cu * sh_u[tid];
    float xi = ci * item_emb[(size_t)tgt * Dd + tid];
    float su_ = xu, squ = xu * xu, si_ = xi, sqi = xi * xi;
    breduce_sum4(su_, squ, si_, sqi, red);
    float mean_u = su_ * (1.0f / Dd);
    float var_u  = squ * (1.0f / Dd) - mean_u * mean_u;
    float mean_i = si_ * (1.0f / Dd);
    float var_i  = sqi * (1.0f / Dd) - mean_i * mean_i;
    float us  = (xu - mean_u) * rsqrtf(var_u + 1e-5f) * ln_u_g[tid] + ln_u_b[tid];
    float is_ = (xi - mean_i) * rsqrtf(var_i + 1e-5f) * ln_i_g[tid] + ln_i_b[tid];

    float pv = us * is_ * pred_W[tid];
    float dot = breduce_sum(pv, red);
    if (tid == 0) out[b] = dot + pred_b[0];
}

// ------------------------------------------- Kernel D: deterministic KL reduce
__global__ __launch_bounds__(256) void kl_reduce_kernel(float* __restrict__ out,
                                                        int out_size) {
    __shared__ float rs[8];
    __shared__ int   ri[8];
    int tid = threadIdx.x;
    float s = 0.f; int c = 0;
    for (int i = tid; i < Bb; i += 256) { s += g_klp[i]; c += g_cnt[i]; }
#pragma unroll
    for (int o = 16; o; o >>= 1) {
        s += __shfl_down_sync(0xffffffffu, s, o);
        c += __shfl_down_sync(0xffffffffu, c, o);
    }
    if ((tid & 31) == 0) { rs[tid >> 5] = s; ri[tid >> 5] = c; }
    __syncthreads();
    if (tid == 0) {
        float S = 0.f; int C = 0;
        for (int i = 0; i < 8; i++) { S += rs[i]; C += ri[i]; }
        if (C < 1) C = 1;
        float kl = 0.25f * S / (float)C;   // BETA * sum / cnt ; (kl_u+kl_i)/2 == kl_u
        if (out_size > Bb) out[Bb] = kl;
    }
}

// ------------------------------------------- launcher
extern "C" void kernel_launch(void* const* d_in, const int* in_sizes, int n_in,
                              void* d_out, int out_size) {
    const float* user_emb = (const float*)d_in[0];
    const float* item_emb = (const float*)d_in[1];
    const float* Wq       = (const float*)d_in[2];
    const float* Wk       = (const float*)d_in[3];
    const float* b_att    = (const float*)d_in[4];
    const float* v_att    = (const float*)d_in[5];
    const float* ln_u_g   = (const float*)d_in[6];
    const float* ln_u_b   = (const float*)d_in[7];
    const float* ln_i_g   = (const float*)d_in[8];
    const float* ln_i_b   = (const float*)d_in[9];
    const float* pred_W   = (const float*)d_in[10];
    const float* pred_b   = (const float*)d_in[11];
    const int* user_hist  = (const int*)d_in[12];
    const int* user_idx   = (const int*)d_in[13];
    const int* item_idx   = (const int*)d_in[14];
    float* out = (float*)d_out;

    static cudaStream_t s1 = nullptr, s2 = nullptr;
    static cudaEvent_t evRoot = nullptr, ev1 = nullptr, ev2 = nullptr;
    if (s1 == nullptr) {
        cudaStreamCreateWithFlags(&s1, cudaStreamNonBlocking);
        cudaStreamCreateWithFlags(&s2, cudaStreamNonBlocking);
        cudaEventCreateWithFlags(&evRoot, cudaEventDisableTiming);
        cudaEventCreateWithFlags(&ev1, cudaEventDisableTiming);
        cudaEventCreateWithFlags(&ev2, cudaEventDisableTiming);
    }

    const int kw_smem = (128 + 2 * 64) * PADU * 4;   // 69632 B
    const int q_smem  = (128 + 32) * PADU * 4;       // 43520 B
    cudaFuncSetAttribute(kw_kernel, cudaFuncAttributeMaxDynamicSharedMemorySize,
                         kw_smem);
    cudaFuncSetAttribute(q_kernel, cudaFuncAttributeMaxDynamicSharedMemorySize,
                         q_smem);

    // fork: eps on s1, q on s2, conv+kw on main stream
    cudaEventRecord(evRoot, 0);
    cudaStreamWaitEvent(s1, evRoot, 0);
    cudaStreamWaitEvent(s2, evRoot, 0);

    eps_kernel<<<(Bb * Ll + 255) / 256, 256, 0, s1>>>();
    q_kernel<<<Bb / 32, 256, q_smem, s2>>>(user_emb, user_idx, Wq, b_att);

    conv_item_kernel<<<1184, 256>>>(item_emb);
    kw_kernel<<<KW_GRID, 256, kw_smem>>>(Wk);

    // join
    cudaEventRecord(ev1, s1);
    cudaEventRecord(ev2, s2);
    cudaStreamWaitEvent(0, ev1, 0);
    cudaStreamWaitEvent(0, ev2, 0);

    fused_kernel<<<Bb, 128>>>(user_emb, item_emb, v_att,
                              ln_u_g, ln_u_b, ln_i_g, ln_i_b,
                              pred_W, pred_b, user_hist, user_idx, item_idx, out);
    kl_reduce_kernel<<<1, 256>>>(out, out_size);
}

// round 15
// speedup vs baseline: 1.8806x; 1.1355x over previous
#include <cuda_runtime.h>
#include <cuda_bf16.h>
#include <stdint.h>

#define Dd 128
#define Ll 200
#define Bb 4096
#define NITEMS 100000

// Scratch (static device globals: allocation-free per harness rules)
__device__ __nv_bfloat16 g_KWh[(NITEMS + 1) * Dd];  // item_emb @ Wk (bf16)
__device__ float g_Q[Bb * Dd];                      // Q = u@Wq + b_att (fp32)
__device__ float g_F1[Bb * Ll];                     // exp(0.1*eps1)
__device__ float g_F2[Bb * Ll];                     // exp(0.1*eps2)
__device__ float g_klp[Bb];
__device__ int   g_cnt[Bb];

// ---------------------------------------------------------------- utilities

__device__ __forceinline__ uint32_t rotl32(uint32_t x, int d) {
    return (x << d) | (x >> (32 - d));
}

// Exact JAX threefry2x32 (20 rounds)
__device__ __forceinline__ void threefry2x32(uint32_t k0, uint32_t k1,
                                             uint32_t c0, uint32_t c1,
                                             uint32_t& o0, uint32_t& o1) {
    uint32_t ks2 = k0 ^ k1 ^ 0x1BD11BDAu;
    uint32_t x0 = c0 + k0, x1 = c1 + k1;
#define TF_R(r) { x0 += x1; x1 = rotl32(x1, r); x1 ^= x0; }
    TF_R(13) TF_R(15) TF_R(26) TF_R(6)  x0 += k1;  x1 += ks2 + 1u;
    TF_R(17) TF_R(29) TF_R(16) TF_R(24) x0 += ks2; x1 += k0 + 2u;
    TF_R(13) TF_R(15) TF_R(26) TF_R(6)  x0 += k0;  x1 += k1 + 3u;
    TF_R(17) TF_R(29) TF_R(16) TF_R(24) x0 += k1;  x1 += ks2 + 4u;
    TF_R(13) TF_R(15) TF_R(26) TF_R(6)  x0 += ks2; x1 += k0 + 5u;
#undef TF_R
    o0 = x0; o1 = x1;
}

// jax.random.normal under jax_threefry_partitionable=True
__device__ __forceinline__ float jax_normal(uint32_t k1, uint32_t idx) {
    uint32_t o0, o1;
    threefry2x32(0u, k1, 0u, idx, o0, o1);
    uint32_t bits = o0 ^ o1;
    float f = __uint_as_float((bits >> 9) | 0x3F800000u) - 1.0f;  // [0,1)
    const float LO = -0.99999994f;                                // nextafter(-1,0)
    float u = fmaf(f, 2.0f, LO);
    u = fmaxf(u, LO);
    return 1.41421356f * erfinvf(u);
}

__device__ __forceinline__ float fast_tanh(float x) {
    float y;
    asm("tanh.approx.f32 %0, %1;" : "=f"(y) : "f"(x));
    return y;
}

__device__ __forceinline__ float breduce_sum(float v, volatile float* red) {
    int tid = threadIdx.x, lane = tid & 31, wrp = tid >> 5;
#pragma unroll
    for (int o = 16; o; o >>= 1) v += __shfl_down_sync(0xffffffffu, v, o);
    if (lane == 0) red[wrp] = v;
    __syncthreads();
    float r = (red[0] + red[1]) + (red[2] + red[3]);
    __syncthreads();
    return r;
}

__device__ __forceinline__ float breduce_max(float v, volatile float* red) {
    int tid = threadIdx.x, lane = tid & 31, wrp = tid >> 5;
#pragma unroll
    for (int o = 16; o; o >>= 1) v = fmaxf(v, __shfl_down_sync(0xffffffffu, v, o));
    if (lane == 0) red[wrp] = v;
    __syncthreads();
    float r = fmaxf(fmaxf(red[0], red[1]), fmaxf(red[2], red[3]));
    __syncthreads();
    return r;
}

// 3-value block sum in one sync round
__device__ __forceinline__ void breduce_sum3(float& a, float& b, float& c,
                                             volatile float* red12) {
    int tid = threadIdx.x, lane = tid & 31, wrp = tid >> 5;
#pragma unroll
    for (int o = 16; o; o >>= 1) {
        a += __shfl_down_sync(0xffffffffu, a, o);
        b += __shfl_down_sync(0xffffffffu, b, o);
        c += __shfl_down_sync(0xffffffffu, c, o);
    }
    if (lane == 0) {
        red12[wrp * 3 + 0] = a;
        red12[wrp * 3 + 1] = b;
        red12[wrp * 3 + 2] = c;
    }
    __syncthreads();
    a = (red12[0] + red12[3]) + (red12[6] + red12[9]);
    b = (red12[1] + red12[4]) + (red12[7] + red12[10]);
    c = (red12[2] + red12[5]) + (red12[8] + red12[11]);
    __syncthreads();
}

// 4-value block sum in one sync round
__device__ __forceinline__ void breduce_sum4(float& a, float& b, float& c, float& d,
                                             volatile float* red16) {
    int tid = threadIdx.x, lane = tid & 31, wrp = tid >> 5;
#pragma unroll
    for (int o = 16; o; o >>= 1) {
        a += __shfl_down_sync(0xffffffffu, a, o);
        b += __shfl_down_sync(0xffffffffu, b, o);
        c += __shfl_down_sync(0xffffffffu, c, o);
        d += __shfl_down_sync(0xffffffffu, d, o);
    }
    if (lane == 0) {
        red16[wrp * 4 + 0] = a;
        red16[wrp * 4 + 1] = b;
        red16[wrp * 4 + 2] = c;
        red16[wrp * 4 + 3] = d;
    }
    __syncthreads();
    a = (red16[0] + red16[4]) + (red16[8] + red16[12]);
    b = (red16[1] + red16[5]) + (red16[9] + red16[13]);
    c = (red16[2] + red16[6]) + (red16[10] + red16[14]);
    d = (red16[3] + red16[7]) + (red16[11] + red16[15]);
    __syncthreads();
}

// ------------------------------------------- Kernel E: precompute lognormal factors
__global__ __launch_bounds__(256) void eps_kernel() {
    int idx = blockIdx.x * 256 + threadIdx.x;
    if (idx < Bb * Ll) {
        float e1 = jax_normal(1u, (uint32_t)idx);
        float e2 = jax_normal(2u, (uint32_t)idx);
        g_F1[idx] = expf(0.1f * e1);
        g_F2[idx] = expf(0.1f * e2);
    }
}

// =================================================================
// bf16 m16n8k16 MMA helpers
//   sW: bf16 k-pairs, row stride PADU uint32
//   sA (kw): fp32, row stride PADW floats (converted at fragment build)
// =================================================================
#define PADU 68
#define PADW 132

// ------------------------------------------- Kernel A: KW = item_emb @ Wk
// fp32 A tiles via cp.async directly from item_emb (no bf16 staging table);
// conversion to bf16 happens at fragment build (bitwise-identical KW output).
// 64-row tiles, grid 296 = 2 blocks/SM (smem 100KB). 8 warps: (wid&3) m-quarter
// of 16 rows, (wid>>2) 64-col half. Double-buffered.
#define KW_GRID 296
#define KW_TILES ((NITEMS + 1 + 63) / 64)   // 1563

__global__ __launch_bounds__(256, 2) void kw_kernel(const float* __restrict__ item_emb,
                                                    const float* __restrict__ Wk) {
    extern __shared__ uint32_t smem_u[];
    uint32_t* sW  = smem_u;                          // [128 n][68] bf16-pairs
    float*    sA0 = (float*)(smem_u + 128 * PADU);   // [64 m][132] fp32
    float*    sA1 = sA0 + 64 * PADW;

    const int tid  = threadIdx.x;
    const int lane = tid & 31;
    const int wid  = tid >> 5;
    const int gid  = lane >> 2;      // 0..7
    const int tig  = lane & 3;       // 0..3
    const int stripe = (wid & 3) * 16;
    const int colh   = (wid >> 2) * 64;

    // sW[n][p] = {bf16(Wk[2p][n]), bf16(Wk[2p+1][n])} — coalesced fill
#pragma unroll 8
    for (int i = tid; i < 64 * 128; i += 256) {
        int p = i >> 7, n = i & 127;
        float a = Wk[(2 * p) * Dd + n];
        float b = Wk[(2 * p + 1) * Dd + n];
        __nv_bfloat162 h = __floats2bfloat162_rn(a, b);
        sW[n * PADU + p] = *(uint32_t*)&h;
    }

    float* bufs[2] = { sA0, sA1 };
    int cur = 0;
    int t = blockIdx.x;

    // async tile loader: 64 rows x 32 16B-chunks (fp32 rows = 512B)
#define LOAD_TILE(dst, tt) do {                                               \
        const int row0_ = (tt) * 64;                                          \
        for (int i = tid; i < 64 * 32; i += 256) {                            \
            int r_ = i >> 5, c_ = i & 31;                                     \
            int sr_ = row0_ + r_; if (sr_ > NITEMS) sr_ = NITEMS;             \
            const float* src_ = item_emb + (size_t)sr_ * Dd + c_ * 4;         \
            uint32_t d_ = (uint32_t)__cvta_generic_to_shared(                 \
                              (dst) + r_ * PADW + c_ * 4);                    \
            asm volatile("cp.async.ca.shared.global [%0], [%1], 16;\n"        \
                         :: "r"(d_), "l"(src_));                              \
        }                                                                     \
    } while (0)

    if (t < KW_TILES) LOAD_TILE(bufs[0], t);
    asm volatile("cp.async.commit_group;\n");

    while (t < KW_TILES) {
        int tn = t + KW_GRID;
        if (tn < KW_TILES) LOAD_TILE(bufs[cur ^ 1], tn);
        asm volatile("cp.async.commit_group;\n");
        asm volatile("cp.async.wait_group 1;\n");
        __syncthreads();

        float* sA = bufs[cur];
        float acc[8][4];
#pragma unroll
        for (int ni = 0; ni < 8; ni++)
#pragma unroll
            for (int j = 0; j < 4; j++) acc[ni][j] = 0.f;

#pragma unroll
        for (int ks = 0; ks < 8; ks++) {
            const int p0 = ks * 8;
            uint32_t a[4];
            {
                int r = stripe + gid;
                // fragment k-pair p covers elements {2p, 2p+1}; fp32 -> bf16x2
                float2 f0 = *(const float2*)(sA + r * PADW + 2 * (p0 + tig));
                float2 f1 = *(const float2*)(sA + (r + 8) * PADW + 2 * (p0 + tig));
                float2 f2 = *(const float2*)(sA + r * PADW + 2 * (p0 + tig + 4));
                float2 f3 = *(const float2*)(sA + (r + 8) * PADW + 2 * (p0 + tig + 4));
                __nv_bfloat162 h0 = __floats2bfloat162_rn(f0.x, f0.y);
                __nv_bfloat162 h1 = __floats2bfloat162_rn(f1.x, f1.y);
                __nv_bfloat162 h2 = __floats2bfloat162_rn(f2.x, f2.y);
                __nv_bfloat162 h3 = __floats2bfloat162_rn(f3.x, f3.y);
                a[0] = *(uint32_t*)&h0;
                a[1] = *(uint32_t*)&h1;
                a[2] = *(uint32_t*)&h2;
                a[3] = *(uint32_t*)&h3;
            }
            uint32_t bf[8][2];
#pragma unroll
            for (int ni = 0; ni < 8; ni++) {
                int n = colh + ni * 8 + gid;
                bf[ni][0] = sW[n * PADU + p0 + tig];
                bf[ni][1] = sW[n * PADU + p0 + tig + 4];
            }
#pragma unroll
            for (int ni = 0; ni < 8; ni++) {
                asm volatile(
                    "mma.sync.aligned.m16n8k16.row.col.f32.bf16.bf16.f32 "
                    "{%0,%1,%2,%3}, {%4,%5,%6,%7}, {%8,%9}, {%0,%1,%2,%3};"
                    : "+f"(acc[ni][0]), "+f"(acc[ni][1]),
                      "+f"(acc[ni][2]), "+f"(acc[ni][3])
                    : "r"(a[0]), "r"(a[1]), "r"(a[2]), "r"(a[3]),
                      "r"(bf[ni][0]), "r"(bf[ni][1]));
            }
        }

        // epilogue: bf16 pack + store
        const int row0 = t * 64;
        uint32_t* kw32 = (uint32_t*)g_KWh;
        {
            int r0 = row0 + stripe + gid;
            int r1 = r0 + 8;
#pragma unroll
            for (int ni = 0; ni < 8; ni++) {
                int c = colh + ni * 8 + tig * 2;
                if (r0 <= NITEMS) {
                    __nv_bfloat162 h = __floats2bfloat162_rn(acc[ni][0], acc[ni][1]);
                    kw32[(size_t)r0 * (Dd / 2) + (c >> 1)] = *(uint32_t*)&h;
                }
                if (r1 <= NITEMS) {
                    __nv_bfloat162 h = __floats2bfloat162_rn(acc[ni][2], acc[ni][3]);
                    kw32[(size_t)r1 * (Dd / 2) + (c >> 1)] = *(uint32_t*)&h;
                }
            }
        }
        __syncthreads();
        cur ^= 1;
        t = tn;
    }
#undef LOAD_TILE
}

// ------------------------------------------- Kernel B: Q = user_emb[uidx] @ Wq + b_att
__global__ __launch_bounds__(256) void q_kernel(const float* __restrict__ user_emb,
                                                const int* __restrict__ user_idx,
                                                const float* __restrict__ Wq,
                                                const float* __restrict__ b_att) {
    extern __shared__ uint32_t smem_u[];
    uint32_t* sW = smem_u;                 // [128 n][68]
    uint32_t* sA = smem_u + 128 * PADU;    // [32 m][68]

    const int tid  = threadIdx.x;
    const int lane = tid & 31;
    const int wid  = tid >> 5;
    const int gid  = lane >> 2;
    const int tig  = lane & 3;
    const int mrow = (wid & 1) * 16;
    const int ncol = (wid >> 1) * 32;
    const int row0 = blockIdx.x * 32;

#pragma unroll 8
    for (int i = tid; i < 64 * 128; i += 256) {
        int p = i >> 7, n = i & 127;
        float a = Wq[(2 * p) * Dd + n];
        float b = Wq[(2 * p + 1) * Dd + n];
        __nv_bfloat162 h = __floats2bfloat162_rn(a, b);
        sW[n * PADU + p] = *(uint32_t*)&h;
    }
#pragma unroll
    for (int i = tid; i < 32 * 64; i += 256) {
        int r = i >> 6, p = i & 63;
        int u = user_idx[row0 + r];
        float2 v = *(const float2*)(user_emb + (size_t)u * Dd + 2 * p);
        __nv_bfloat162 h = __floats2bfloat162_rn(v.x, v.y);
        sA[r * PADU + p] = *(uint32_t*)&h;
    }
    __syncthreads();

    float acc[4][4];
#pragma unroll
    for (int ni = 0; ni < 4; ni++)
#pragma unroll
        for (int j = 0; j < 4; j++) acc[ni][j] = 0.f;

#pragma unroll
    for (int ks = 0; ks < 8; ks++) {
        const int p0 = ks * 8;
        uint32_t a[4];
        a[0] = sA[(mrow + gid) * PADU + p0 + tig];
        a[1] = sA[(mrow + 8 + gid) * PADU + p0 + tig];
        a[2] = sA[(mrow + gid) * PADU + p0 + tig + 4];
        a[3] = sA[(mrow + 8 + gid) * PADU + p0 + tig + 4];
        uint32_t bf[4][2];
#pragma unroll
        for (int ni = 0; ni < 4; ni++) {
            int n = ncol + ni * 8 + gid;
            bf[ni][0] = sW[n * PADU + p0 + tig];
            bf[ni][1] = sW[n * PADU + p0 + tig + 4];
        }
#pragma unroll
        for (int ni = 0; ni < 4; ni++) {
            asm volatile(
                "mma.sync.aligned.m16n8k16.row.col.f32.bf16.bf16.f32 "
                "{%0,%1,%2,%3}, {%4,%5,%6,%7}, {%8,%9}, {%0,%1,%2,%3};"
                : "+f"(acc[ni][0]), "+f"(acc[ni][1]),
                  "+f"(acc[ni][2]), "+f"(acc[ni][3])
                : "r"(a[0]), "r"(a[1]), "r"(a[2]), "r"(a[3]),
                  "r"(bf[ni][0]), "r"(bf[ni][1]));
        }
    }

    {
        int r0 = row0 + mrow + gid;
        int r1 = r0 + 8;
#pragma unroll
        for (int ni = 0; ni < 4; ni++) {
            int c = ncol + ni * 8 + tig * 2;
            float2 ba = *(const float2*)(b_att + c);
            *(float2*)(g_Q + (size_t)r0 * Dd + c) =
                make_float2(acc[ni][0] + ba.x, acc[ni][1] + ba.y);
            *(float2*)(g_Q + (size_t)r1 * Dd + c) =
                make_float2(acc[ni][2] + ba.x, acc[ni][3] + ba.y);
        }
    }
}

// ------------------------------------------- Kernel C: fused BAM forward
__global__ __launch_bounds__(128, 8) void fused_kernel(
    const float* __restrict__ user_emb,
    const float* __restrict__ item_emb,
    const float* __restrict__ v_att,
    const float* __restrict__ ln_u_g, const float* __restrict__ ln_u_b,
    const float* __restrict__ ln_i_g, const float* __restrict__ ln_i_b,
    const float* __restrict__ pred_W, const float* __restrict__ pred_b,
    const int* __restrict__ user_hist,
    const int* __restrict__ user_idx,
    const int* __restrict__ item_idx,
    float* __restrict__ out)
{
    __shared__ __align__(16) float sh_q[Dd];
    __shared__ __align__(16) float sh_u[Dd];
    __shared__ __align__(16) float sh_v[Dd];
    __shared__ int   sh_r[Ll];
    __shared__ float sh_s[Ll];
    __shared__ float sh_w1[Ll];
    __shared__ float sh_w2[Ll];
    __shared__ float red[16];
    __shared__ __align__(16) float sred[2][4][Dd];   // cross-warp ctx partials

    const int tid  = threadIdx.x;
    const int lane = tid & 31;
    const int wrp  = tid >> 5;
    const int b    = blockIdx.x;
    const int uidx = user_idx[b];
    const int tgt  = item_idx[b];

    sh_u[tid] = user_emb[(size_t)uidx * Dd + tid];
    sh_q[tid] = g_Q[(size_t)b * Dd + tid];     // includes b_att
    sh_v[tid] = v_att[tid];
    float validf = 0.f;
    for (int l = tid; l < Ll; l += 128) {
        int r = user_hist[(size_t)uidx * Ll + l];
        bool ok = (r != tgt) && (r != NITEMS);
        sh_r[l] = ok ? r : -1;
        validf += ok ? 1.f : 0.f;
    }
    __syncthreads();

    float nvf = breduce_sum(validf, red);
    int n_valid = (int)(nvf + 0.5f);
    float nv_clamped = (n_valid > 0) ? (float)n_valid : 1.0f;
    float mu_p = -logf(nv_clamped);

    // scores: warp per l, 4 rows/iteration (4 independent shfl chains overlap)
    float4 q4, v4;
    {
        float2 qa = *(const float2*)(sh_q + lane * 4);
        float2 qb = *(const float2*)(sh_q + lane * 4 + 2);
        q4 = make_float4(qa.x, qa.y, qb.x, qb.y);
        float2 va = *(const float2*)(sh_v + lane * 4);
        float2 vb = *(const float2*)(sh_v + lane * 4 + 2);
        v4 = make_float4(va.x, va.y, vb.x, vb.y);
    }
    for (int l = wrp; l < Ll; l += 16) {
        int rs0 = sh_r[l];
        int rs1 = (l + 4  < Ll) ? sh_r[l + 4]  : -1;
        int rs2 = (l + 8  < Ll) ? sh_r[l + 8]  : -1;
        int rs3 = (l + 12 < Ll) ? sh_r[l + 12] : -1;
        uint2 raw0 = make_uint2(0u, 0u), raw1 = make_uint2(0u, 0u);
        uint2 raw2 = make_uint2(0u, 0u), raw3 = make_uint2(0u, 0u);
        if (rs0 >= 0) raw0 = ((const uint2*)(g_KWh + (size_t)rs0 * Dd))[lane];
        if (rs1 >= 0) raw1 = ((const uint2*)(g_KWh + (size_t)rs1 * Dd))[lane];
        if (rs2 >= 0) raw2 = ((const uint2*)(g_KWh + (size_t)rs2 * Dd))[lane];
        if (rs3 >= 0) raw3 = ((const uint2*)(g_KWh + (size_t)rs3 * Dd))[lane];

        float t0 = 0.f, t1 = 0.f, t2 = 0.f, t3 = 0.f;
        {
            float2 f0 = __bfloat1622float2(*(__nv_bfloat162*)&raw0.x);
            float2 f1 = __bfloat1622float2(*(__nv_bfloat162*)&raw0.y);
            t0 = v4.x * fast_tanh(q4.x + f0.x);
            t0 = fmaf(v4.y, fast_tanh(q4.y + f0.y), t0);
            t0 = fmaf(v4.z, fast_tanh(q4.z + f1.x), t0);
            t0 = fmaf(v4.w, fast_tanh(q4.w + f1.y), t0);
        }
        {
            float2 f0 = __bfloat1622float2(*(__nv_bfloat162*)&raw1.x);
            float2 f1 = __bfloat1622float2(*(__nv_bfloat162*)&raw1.y);
            t1 = v4.x * fast_tanh(q4.x + f0.x);
            t1 = fmaf(v4.y, fast_tanh(q4.y + f0.y), t1);
            t1 = fmaf(v4.z, fast_tanh(q4.z + f1.x), t1);
            t1 = fmaf(v4.w, fast_tanh(q4.w + f1.y), t1);
        }
        {
            float2 f0 = __bfloat1622float2(*(__nv_bfloat162*)&raw2.x);
            float2 f1 = __bfloat1622float2(*(__nv_bfloat162*)&raw2.y);
            t2 = v4.x * fast_tanh(q4.x + f0.x);
            t2 = fmaf(v4.y, fast_tanh(q4.y + f0.y), t2);
            t2 = fmaf(v4.z, fast_tanh(q4.z + f1.x), t2);
            t2 = fmaf(v4.w, fast_tanh(q4.w + f1.y), t2);
        }
        {
            float2 f0 = __bfloat1622float2(*(__nv_bfloat162*)&raw3.x);
            float2 f1 = __bfloat1622float2(*(__nv_bfloat162*)&raw3.y);
            t3 = v4.x * fast_tanh(q4.x + f0.x);
            t3 = fmaf(v4.y, fast_tanh(q4.y + f0.y), t3);
            t3 = fmaf(v4.z, fast_tanh(q4.z + f1.x), t3);
            t3 = fmaf(v4.w, fast_tanh(q4.w + f1.y), t3);
        }
#pragma unroll
        for (int o = 16; o; o >>= 1) {
            t0 += __shfl_down_sync(0xffffffffu, t0, o);
            t1 += __shfl_down_sync(0xffffffffu, t1, o);
            t2 += __shfl_down_sync(0xffffffffu, t2, o);
            t3 += __shfl_down_sync(0xffffffffu, t3, o);
        }
        if (lane == 0) {
            sh_s[l] = (rs0 >= 0) ? t0 * 0.25f : -1e30f;
            if (l + 4  < Ll) sh_s[l + 4]  = (rs1 >= 0) ? t1 * 0.25f : -1e30f;
            if (l + 8  < Ll) sh_s[l + 8]  = (rs2 >= 0) ? t2 * 0.25f : -1e30f;
            if (l + 12 < Ll) sh_s[l + 12] = (rs3 >= 0) ? t3 * 0.25f : -1e30f;
        }
    }
    __syncthreads();

    // softmax
    float m = -1e30f;
    for (int l = tid; l < Ll; l += 128) m = fmaxf(m, sh_s[l]);
    m = breduce_max(m, red);

    float esum = 0.f;
    for (int l = tid; l < Ll; l += 128) {
        float e = 0.f;
        if (sh_r[l] >= 0) e = expf(sh_s[l] - m);
        sh_s[l] = e;
        esum += e;
    }
    esum = breduce_sum(esum, red);
    float inv_es = (esum > 0.f) ? (1.0f / esum) : 0.f;

    // sampled weights via precomputed lognormal factors + KL; triple reduce
    float klacc = 0.f, s1 = 0.f, s2 = 0.f;
    for (int l = tid; l < Ll; l += 128) {
        float w1 = 0.f, w2 = 0.f;
        if (sh_r[l] >= 0) {
            float alpha = sh_s[l] * inv_es;
            float ap = alpha + 1e-24f;
            float mu = logf(ap);
            int idx = b * Ll + l;
            w1 = ap * g_F1[idx];
            w2 = ap * g_F2[idx];
            float dmu = mu - mu_p;
            klacc += 1.8075851f + 0.5f * dmu * dmu;  // log(10)-0.5+SIG_Q^2/2 + d^2/2
        }
        sh_w1[l] = w1;
        sh_w2[l] = w2;
        s1 += w1;
        s2 += w2;
    }
    breduce_sum3(klacc, s1, s2, red);
    if (tid == 0) { g_klp[b] = klacc; g_cnt[b] = n_valid; }
    float i1 = 1.0f / (s1 + 1e-12f);
    float i2 = 1.0f / (s2 + 1e-12f);

    // contexts: warp-per-row gather with LDG.128 (value path stays fp32)
    {
        float4 cu4 = make_float4(0.f, 0.f, 0.f, 0.f);
        float4 ci4 = make_float4(0.f, 0.f, 0.f, 0.f);
        const int lbase = wrp * 50;
#pragma unroll 5
        for (int j = 0; j < 50; j += 2) {
            int l0 = lbase + j, l1 = l0 + 1;
            int r0 = sh_r[l0], r1 = sh_r[l1];
            float4 v0 = make_float4(0.f, 0.f, 0.f, 0.f);
            float4 v1 = make_float4(0.f, 0.f, 0.f, 0.f);
            if (r0 >= 0) v0 = ((const float4*)(item_emb + (size_t)r0 * Dd))[lane];
            if (r1 >= 0) v1 = ((const float4*)(item_emb + (size_t)r1 * Dd))[lane];
            float w10 = sh_w1[l0], w20 = sh_w2[l0];
            float w11 = sh_w1[l1], w21 = sh_w2[l1];
            cu4.x = fmaf(w10, v0.x, fmaf(w11, v1.x, cu4.x));
            cu4.y = fmaf(w10, v0.y, fmaf(w11, v1.y, cu4.y));
            cu4.z = fmaf(w10, v0.z, fmaf(w11, v1.z, cu4.z));
            cu4.w = fmaf(w10, v0.w, fmaf(w11, v1.w, cu4.w));
            ci4.x = fmaf(w20, v0.x, fmaf(w21, v1.x, ci4.x));
            ci4.y = fmaf(w20, v0.y, fmaf(w21, v1.y, ci4.y));
            ci4.z = fmaf(w20, v0.z, fmaf(w21, v1.z, ci4.z));
            ci4.w = fmaf(w20, v0.w, fmaf(w21, v1.w, ci4.w));
        }
        *(float4*)&sred[0][wrp][lane * 4] = cu4;
        *(float4*)&sred[1][wrp][lane * 4] = ci4;
    }
    __syncthreads();
    float cu = (sred[0][0][tid] + sred[0][1][tid]) +
               (sred[0][2][tid] + sred[0][3][tid]);
    float ci = (sred[1][0][tid] + sred[1][1][tid]) +
               (sred[1][2][tid] + sred[1][3][tid]);
    cu *= i1; ci *= i2;

    // both layernorms via sum/sumsq, single 4-value reduce round
    float xu = cu * sh_u[tid];
    float xi = ci * item_emb[(size_t)tgt * Dd + tid];
    float su_ = xu, squ = xu * xu, si_ = xi, sqi = xi * xi;
    breduce_sum4(su_, squ, si_, sqi, red);
    float mean_u = su_ * (1.0f / Dd);
    float var_u  = squ * (1.0f / Dd) - mean_u * mean_u;
    float mean_i = si_ * (1.0f / Dd);
    float var_i  = sqi * (1.0f / Dd) - mean_i * mean_i;
    float us  = (xu - mean_u) * rsqrtf(var_u + 1e-5f) * ln_u_g[tid] + ln_u_b[tid];
    float is_ = (xi - mean_i) * rsqrtf(var_i + 1e-5f) * ln_i_g[tid] + ln_i_b[tid];

    float pv = us * is_ * pred_W[tid];
    float dot = breduce_sum(pv, red);
    if (tid == 0) out[b] = dot + pred_b[0];
}

// ------------------------------------------- Kernel D: deterministic KL reduce
__global__ __launch_bounds__(256) void kl_reduce_kernel(float* __restrict__ out,
                                                        int out_size) {
    __shared__ float rs[8];
    __shared__ int   ri[8];
    int tid = threadIdx.x;
    float s = 0.f; int c = 0;
    for (int i = tid; i < Bb; i += 256) { s += g_klp[i]; c += g_cnt[i]; }
#pragma unroll
    for (int o = 16; o; o >>= 1) {
        s += __shfl_down_sync(0xffffffffu, s, o);
        c += __shfl_down_sync(0xffffffffu, c, o);
    }
    if ((tid & 31) == 0) { rs[tid >> 5] = s; ri[tid >> 5] = c; }
    __syncthreads();
    if (tid == 0) {
        float S = 0.f; int C = 0;
        for (int i = 0; i < 8; i++) { S += rs[i]; C += ri[i]; }
        if (C < 1) C = 1;
        float kl = 0.25f * S / (float)C;   // BETA * sum / cnt ; (kl_u+kl_i)/2 == kl_u
        if (out_size > Bb) out[Bb] = kl;
    }
}

// ------------------------------------------- launcher
extern "C" void kernel_launch(void* const* d_in, const int* in_sizes, int n_in,
                              void* d_out, int out_size) {
    const float* user_emb = (const float*)d_in[0];
    const float* item_emb = (const float*)d_in[1];
    const float* Wq       = (const float*)d_in[2];
    const float* Wk       = (const float*)d_in[3];
    const float* b_att    = (const float*)d_in[4];
    const float* v_att    = (const float*)d_in[5];
    const float* ln_u_g   = (const float*)d_in[6];
    const float* ln_u_b   = (const float*)d_in[7];
    const float* ln_i_g   = (const float*)d_in[8];
    const float* ln_i_b   = (const float*)d_in[9];
    const float* pred_W   = (const float*)d_in[10];
    const float* pred_b   = (const float*)d_in[11];
    const int* user_hist  = (const int*)d_in[12];
    const int* user_idx   = (const int*)d_in[13];
    const int* item_idx   = (const int*)d_in[14];
    float* out = (float*)d_out;

    static cudaStream_t s1 = nullptr, s2 = nullptr;
    static cudaEvent_t evRoot = nullptr, ev1 = nullptr, ev2 = nullptr;
    if (s1 == nullptr) {
        cudaStreamCreateWithFlags(&s1, cudaStreamNonBlocking);
        cudaStreamCreateWithFlags(&s2, cudaStreamNonBlocking);
        cudaEventCreateWithFlags(&evRoot, cudaEventDisableTiming);
        cudaEventCreateWithFlags(&ev1, cudaEventDisableTiming);
        cudaEventCreateWithFlags(&ev2, cudaEventDisableTiming);
    }

    const int kw_smem = 128 * PADU * 4 + 2 * 64 * PADW * 4;   // 34816+67584=102400 B
    const int q_smem  = (128 + 32) * PADU * 4;                // 43520 B
    cudaFuncSetAttribute(kw_kernel, cudaFuncAttributeMaxDynamicSharedMemorySize,
                         kw_smem);
    cudaFuncSetAttribute(q_kernel, cudaFuncAttributeMaxDynamicSharedMemorySize,
                         q_smem);

    // fork: eps on s1, q on s2, kw on main stream
    cudaEventRecord(evRoot, 0);
    cudaStreamWaitEvent(s1, evRoot, 0);
    cudaStreamWaitEvent(s2, evRoot, 0);

    eps_kernel<<<(Bb * Ll + 255) / 256, 256, 0, s1>>>();
    q_kernel<<<Bb / 32, 256, q_smem, s2>>>(user_emb, user_idx, Wq, b_att);

    kw_kernel<<<KW_GRID, 256, kw_smem>>>(item_emb, Wk);

    // join
    cudaEventRecord(ev1, s1);
    cudaEventRecord(ev2, s2);
    cudaStreamWaitEvent(0, ev1, 0);
    cudaStreamWaitEvent(0, ev2, 0);

    fused_kernel<<<Bb, 128>>>(user_emb, item_emb, v_att,
                              ln_u_g, ln_u_b, ln_i_g, ln_i_b,
                              pred_W, pred_b, user_hist, user_idx, item_idx, out);
    kl_reduce_kernel<<<1, 256>>>(out, out_size);
}

// round 16
// speedup vs baseline: 1.9705x; 1.0478x over previous
#include <cuda_runtime.h>
#include <cuda_bf16.h>
#include <stdint.h>

#define Dd 128
#define Ll 200
#define Bb 4096
#define NITEMS 100000

// Scratch (static device globals: allocation-free per harness rules)
__device__ __nv_bfloat16 g_KWh[(NITEMS + 1) * Dd];  // item_emb @ Wk (bf16)
__device__ float g_Q[Bb * Dd];                      // Q = u@Wq + b_att (fp32)
__device__ float2 g_F12[Bb * Ll];                   // {exp(0.1*eps1), exp(0.1*eps2)}
__device__ float g_klp[Bb];
__device__ int   g_cnt[Bb];

// ---------------------------------------------------------------- utilities

__device__ __forceinline__ uint32_t rotl32(uint32_t x, int d) {
    return (x << d) | (x >> (32 - d));
}

// Exact JAX threefry2x32 (20 rounds)
__device__ __forceinline__ void threefry2x32(uint32_t k0, uint32_t k1,
                                             uint32_t c0, uint32_t c1,
                                             uint32_t& o0, uint32_t& o1) {
    uint32_t ks2 = k0 ^ k1 ^ 0x1BD11BDAu;
    uint32_t x0 = c0 + k0, x1 = c1 + k1;
#define TF_R(r) { x0 += x1; x1 = rotl32(x1, r); x1 ^= x0; }
    TF_R(13) TF_R(15) TF_R(26) TF_R(6)  x0 += k1;  x1 += ks2 + 1u;
    TF_R(17) TF_R(29) TF_R(16) TF_R(24) x0 += ks2; x1 += k0 + 2u;
    TF_R(13) TF_R(15) TF_R(26) TF_R(6)  x0 += k0;  x1 += k1 + 3u;
    TF_R(17) TF_R(29) TF_R(16) TF_R(24) x0 += k1;  x1 += ks2 + 4u;
    TF_R(13) TF_R(15) TF_R(26) TF_R(6)  x0 += ks2; x1 += k0 + 5u;
#undef TF_R
    o0 = x0; o1 = x1;
}

// jax.random.normal under jax_threefry_partitionable=True
__device__ __forceinline__ float jax_normal(uint32_t k1, uint32_t idx) {
    uint32_t o0, o1;
    threefry2x32(0u, k1, 0u, idx, o0, o1);
    uint32_t bits = o0 ^ o1;
    float f = __uint_as_float((bits >> 9) | 0x3F800000u) - 1.0f;  // [0,1)
    const float LO = -0.99999994f;                                // nextafter(-1,0)
    float u = fmaf(f, 2.0f, LO);
    u = fmaxf(u, LO);
    return 1.41421356f * erfinvf(u);
}

__device__ __forceinline__ float breduce_sum(float v, volatile float* red) {
    int tid = threadIdx.x, lane = tid & 31, wrp = tid >> 5;
#pragma unroll
    for (int o = 16; o; o >>= 1) v += __shfl_down_sync(0xffffffffu, v, o);
    if (lane == 0) red[wrp] = v;
    __syncthreads();
    float r = (red[0] + red[1]) + (red[2] + red[3]);
    __syncthreads();
    return r;
}

__device__ __forceinline__ float breduce_max(float v, volatile float* red) {
    int tid = threadIdx.x, lane = tid & 31, wrp = tid >> 5;
#pragma unroll
    for (int o = 16; o; o >>= 1) v = fmaxf(v, __shfl_down_sync(0xffffffffu, v, o));
    if (lane == 0) red[wrp] = v;
    __syncthreads();
    float r = fmaxf(fmaxf(red[0], red[1]), fmaxf(red[2], red[3]));
    __syncthreads();
    return r;
}

// 3-value block sum in one sync round
__device__ __forceinline__ void breduce_sum3(float& a, float& b, float& c,
                                             volatile float* red12) {
    int tid = threadIdx.x, lane = tid & 31, wrp = tid >> 5;
#pragma unroll
    for (int o = 16; o; o >>= 1) {
        a += __shfl_down_sync(0xffffffffu, a, o);
        b += __shfl_down_sync(0xffffffffu, b, o);
        c += __shfl_down_sync(0xffffffffu, c, o);
    }
    if (lane == 0) {
        red12[wrp * 3 + 0] = a;
        red12[wrp * 3 + 1] = b;
        red12[wrp * 3 + 2] = c;
    }
    __syncthreads();
    a = (red12[0] + red12[3]) + (red12[6] + red12[9]);
    b = (red12[1] + red12[4]) + (red12[7] + red12[10]);
    c = (red12[2] + red12[5]) + (red12[8] + red12[11]);
    __syncthreads();
}

// 4-value block sum in one sync round
__device__ __forceinline__ void breduce_sum4(float& a, float& b, float& c, float& d,
                                             volatile float* red16) {
    int tid = threadIdx.x, lane = tid & 31, wrp = tid >> 5;
#pragma unroll
    for (int o = 16; o; o >>= 1) {
        a += __shfl_down_sync(0xffffffffu, a, o);
        b += __shfl_down_sync(0xffffffffu, b, o);
        c += __shfl_down_sync(0xffffffffu, c, o);
        d += __shfl_down_sync(0xffffffffu, d, o);
    }
    if (lane == 0) {
        red16[wrp * 4 + 0] = a;
        red16[wrp * 4 + 1] = b;
        red16[wrp * 4 + 2] = c;
        red16[wrp * 4 + 3] = d;
    }
    __syncthreads();
    a = (red16[0] + red16[4]) + (red16[8] + red16[12]);
    b = (red16[1] + red16[5]) + (red16[9] + red16[13]);
    c = (red16[2] + red16[6]) + (red16[10] + red16[14]);
    d = (red16[3] + red16[7]) + (red16[11] + red16[15]);
    __syncthreads();
}

// ------------------------------------------- Kernel E: precompute lognormal factors
__global__ __launch_bounds__(256) void eps_kernel() {
    int idx = blockIdx.x * 256 + threadIdx.x;
    if (idx < Bb * Ll) {
        float e1 = jax_normal(1u, (uint32_t)idx);
        float e2 = jax_normal(2u, (uint32_t)idx);
        g_F12[idx] = make_float2(expf(0.1f * e1), expf(0.1f * e2));
    }
}

// =================================================================
// bf16 m16n8k16 MMA helpers
// =================================================================
#define PADU 68
#define PADW 132

// ------------------------------------------- Kernel A: KW = item_emb @ Wk
// fp32 A tiles via cp.async directly from item_emb; bf16 convert at fragment
// build. 64-row tiles, grid 296 = 2 blocks/SM. Double-buffered.
#define KW_GRID 296
#define KW_TILES ((NITEMS + 1 + 63) / 64)   // 1563

__global__ __launch_bounds__(256, 2) void kw_kernel(const float* __restrict__ item_emb,
                                                    const float* __restrict__ Wk) {
    extern __shared__ uint32_t smem_u[];
    uint32_t* sW  = smem_u;                          // [128 n][68] bf16-pairs
    float*    sA0 = (float*)(smem_u + 128 * PADU);   // [64 m][132] fp32
    float*    sA1 = sA0 + 64 * PADW;

    const int tid  = threadIdx.x;
    const int lane = tid & 31;
    const int wid  = tid >> 5;
    const int gid  = lane >> 2;      // 0..7
    const int tig  = lane & 3;       // 0..3
    const int stripe = (wid & 3) * 16;
    const int colh   = (wid >> 2) * 64;

    // sW[n][p] = {bf16(Wk[2p][n]), bf16(Wk[2p+1][n])} — coalesced fill
#pragma unroll 8
    for (int i = tid; i < 64 * 128; i += 256) {
        int p = i >> 7, n = i & 127;
        float a = Wk[(2 * p) * Dd + n];
        float b = Wk[(2 * p + 1) * Dd + n];
        __nv_bfloat162 h = __floats2bfloat162_rn(a, b);
        sW[n * PADU + p] = *(uint32_t*)&h;
    }

    float* bufs[2] = { sA0, sA1 };
    int cur = 0;
    int t = blockIdx.x;

#define LOAD_TILE(dst, tt) do {                                               \
        const int row0_ = (tt) * 64;                                          \
        for (int i = tid; i < 64 * 32; i += 256) {                            \
            int r_ = i >> 5, c_ = i & 31;                                     \
            int sr_ = row0_ + r_; if (sr_ > NITEMS) sr_ = NITEMS;             \
            const float* src_ = item_emb + (size_t)sr_ * Dd + c_ * 4;         \
            uint32_t d_ = (uint32_t)__cvta_generic_to_shared(                 \
                              (dst) + r_ * PADW + c_ * 4);                    \
            asm volatile("cp.async.ca.shared.global [%0], [%1], 16;\n"        \
                         :: "r"(d_), "l"(src_));                              \
        }                                                                     \
    } while (0)

    if (t < KW_TILES) LOAD_TILE(bufs[0], t);
    asm volatile("cp.async.commit_group;\n");

    while (t < KW_TILES) {
        int tn = t + KW_GRID;
        if (tn < KW_TILES) LOAD_TILE(bufs[cur ^ 1], tn);
        asm volatile("cp.async.commit_group;\n");
        asm volatile("cp.async.wait_group 1;\n");
        __syncthreads();

        float* sA = bufs[cur];
        float acc[8][4];
#pragma unroll
        for (int ni = 0; ni < 8; ni++)
#pragma unroll
            for (int j = 0; j < 4; j++) acc[ni][j] = 0.f;

#pragma unroll
        for (int ks = 0; ks < 8; ks++) {
            const int p0 = ks * 8;
            uint32_t a[4];
            {
                int r = stripe + gid;
                float2 f0 = *(const float2*)(sA + r * PADW + 2 * (p0 + tig));
                float2 f1 = *(const float2*)(sA + (r + 8) * PADW + 2 * (p0 + tig));
                float2 f2 = *(const float2*)(sA + r * PADW + 2 * (p0 + tig + 4));
                float2 f3 = *(const float2*)(sA + (r + 8) * PADW + 2 * (p0 + tig + 4));
                __nv_bfloat162 h0 = __floats2bfloat162_rn(f0.x, f0.y);
                __nv_bfloat162 h1 = __floats2bfloat162_rn(f1.x, f1.y);
                __nv_bfloat162 h2 = __floats2bfloat162_rn(f2.x, f2.y);
                __nv_bfloat162 h3 = __floats2bfloat162_rn(f3.x, f3.y);
                a[0] = *(uint32_t*)&h0;
                a[1] = *(uint32_t*)&h1;
                a[2] = *(uint32_t*)&h2;
                a[3] = *(uint32_t*)&h3;
            }
            uint32_t bf[8][2];
#pragma unroll
            for (int ni = 0; ni < 8; ni++) {
                int n = colh + ni * 8 + gid;
                bf[ni][0] = sW[n * PADU + p0 + tig];
                bf[ni][1] = sW[n * PADU + p0 + tig + 4];
            }
#pragma unroll
            for (int ni = 0; ni < 8; ni++) {
                asm volatile(
                    "mma.sync.aligned.m16n8k16.row.col.f32.bf16.bf16.f32 "
                    "{%0,%1,%2,%3}, {%4,%5,%6,%7}, {%8,%9}, {%0,%1,%2,%3};"
                    : "+f"(acc[ni][0]), "+f"(acc[ni][1]),
                      "+f"(acc[ni][2]), "+f"(acc[ni][3])
                    : "r"(a[0]), "r"(a[1]), "r"(a[2]), "r"(a[3]),
                      "r"(bf[ni][0]), "r"(bf[ni][1]));
            }
        }

        // epilogue: bf16 pack + store
        const int row0 = t * 64;
        uint32_t* kw32 = (uint32_t*)g_KWh;
        {
            int r0 = row0 + stripe + gid;
            int r1 = r0 + 8;
#pragma unroll
            for (int ni = 0; ni < 8; ni++) {
                int c = colh + ni * 8 + tig * 2;
                if (r0 <= NITEMS) {
                    __nv_bfloat162 h = __floats2bfloat162_rn(acc[ni][0], acc[ni][1]);
                    kw32[(size_t)r0 * (Dd / 2) + (c >> 1)] = *(uint32_t*)&h;
                }
                if (r1 <= NITEMS) {
                    __nv_bfloat162 h = __floats2bfloat162_rn(acc[ni][2], acc[ni][3]);
                    kw32[(size_t)r1 * (Dd / 2) + (c >> 1)] = *(uint32_t*)&h;
                }
            }
        }
        __syncthreads();
        cur ^= 1;
        t = tn;
    }
#undef LOAD_TILE
}

// ------------------------------------------- Kernel B: Q = user_emb[uidx] @ Wq + b_att
__global__ __launch_bounds__(256) void q_kernel(const float* __restrict__ user_emb,
                                                const int* __restrict__ user_idx,
                                                const float* __restrict__ Wq,
                                                const float* __restrict__ b_att) {
    extern __shared__ uint32_t smem_u[];
    uint32_t* sW = smem_u;                 // [128 n][68]
    uint32_t* sA = smem_u + 128 * PADU;    // [32 m][68]

    const int tid  = threadIdx.x;
    const int lane = tid & 31;
    const int wid  = tid >> 5;
    const int gid  = lane >> 2;
    const int tig  = lane & 3;
    const int mrow = (wid & 1) * 16;
    const int ncol = (wid >> 1) * 32;
    const int row0 = blockIdx.x * 32;

#pragma unroll 8
    for (int i = tid; i < 64 * 128; i += 256) {
        int p = i >> 7, n = i & 127;
        float a = Wq[(2 * p) * Dd + n];
        float b = Wq[(2 * p + 1) * Dd + n];
        __nv_bfloat162 h = __floats2bfloat162_rn(a, b);
        sW[n * PADU + p] = *(uint32_t*)&h;
    }
#pragma unroll
    for (int i = tid; i < 32 * 64; i += 256) {
        int r = i >> 6, p = i & 63;
        int u = user_idx[row0 + r];
        float2 v = *(const float2*)(user_emb + (size_t)u * Dd + 2 * p);
        __nv_bfloat162 h = __floats2bfloat162_rn(v.x, v.y);
        sA[r * PADU + p] = *(uint32_t*)&h;
    }
    __syncthreads();

    float acc[4][4];
#pragma unroll
    for (int ni = 0; ni < 4; ni++)
#pragma unroll
        for (int j = 0; j < 4; j++) acc[ni][j] = 0.f;

#pragma unroll
    for (int ks = 0; ks < 8; ks++) {
        const int p0 = ks * 8;
        uint32_t a[4];
        a[0] = sA[(mrow + gid) * PADU + p0 + tig];
        a[1] = sA[(mrow + 8 + gid) * PADU + p0 + tig];
        a[2] = sA[(mrow + gid) * PADU + p0 + tig + 4];
        a[3] = sA[(mrow + 8 + gid) * PADU + p0 + tig + 4];
        uint32_t bf[4][2];
#pragma unroll
        for (int ni = 0; ni < 4; ni++) {
            int n = ncol + ni * 8 + gid;
            bf[ni][0] = sW[n * PADU + p0 + tig];
            bf[ni][1] = sW[n * PADU + p0 + tig + 4];
        }
#pragma unroll
        for (int ni = 0; ni < 4; ni++) {
            asm volatile(
                "mma.sync.aligned.m16n8k16.row.col.f32.bf16.bf16.f32 "
                "{%0,%1,%2,%3}, {%4,%5,%6,%7}, {%8,%9}, {%0,%1,%2,%3};"
                : "+f"(acc[ni][0]), "+f"(acc[ni][1]),
                  "+f"(acc[ni][2]), "+f"(acc[ni][3])
                : "r"(a[0]), "r"(a[1]), "r"(a[2]), "r"(a[3]),
                  "r"(bf[ni][0]), "r"(bf[ni][1]));
        }
    }

    {
        int r0 = row0 + mrow + gid;
        int r1 = r0 + 8;
#pragma unroll
        for (int ni = 0; ni < 4; ni++) {
            int c = ncol + ni * 8 + tig * 2;
            float2 ba = *(const float2*)(b_att + c);
            *(float2*)(g_Q + (size_t)r0 * Dd + c) =
                make_float2(acc[ni][0] + ba.x, acc[ni][1] + ba.y);
            *(float2*)(g_Q + (size_t)r1 * Dd + c) =
                make_float2(acc[ni][2] + ba.x, acc[ni][3] + ba.y);
        }
    }
}

// bf16x2 helpers for score path
__device__ __forceinline__ uint32_t badd2(uint32_t a, uint32_t b) {
    uint32_t r;
    asm("add.rn.bf16x2 %0, %1, %2;" : "=r"(r) : "r"(a), "r"(b));
    return r;
}
__device__ __forceinline__ uint32_t btanh2(uint32_t a) {
    uint32_t r;
    asm("tanh.approx.bf16x2 %0, %1;" : "=r"(r) : "r"(a));
    return r;
}

// ------------------------------------------- Kernel C: fused BAM forward
__global__ __launch_bounds__(128, 10) void fused_kernel(
    const float* __restrict__ user_emb,
    const float* __restrict__ item_emb,
    const float* __restrict__ v_att,
    const float* __restrict__ ln_u_g, const float* __restrict__ ln_u_b,
    const float* __restrict__ ln_i_g, const float* __restrict__ ln_i_b,
    const float* __restrict__ pred_W, const float* __restrict__ pred_b,
    const int* __restrict__ user_hist,
    const int* __restrict__ user_idx,
    const int* __restrict__ item_idx,
    float* __restrict__ out)
{
    __shared__ __align__(16) float sh_u[Dd];
    __shared__ int   sh_r[Ll];
    __shared__ float sh_s[Ll];
    __shared__ float sh_w1[Ll];
    __shared__ float sh_w2[Ll];
    __shared__ float red[16];
    __shared__ __align__(16) float sred[2][4][Dd];   // cross-warp ctx partials

    const int tid  = threadIdx.x;
    const int lane = tid & 31;
    const int wrp  = tid >> 5;
    const int b    = blockIdx.x;
    const int uidx = user_idx[b];
    const int tgt  = item_idx[b];

    sh_u[tid] = user_emb[(size_t)uidx * Dd + tid];
    float validf = 0.f;
    for (int l = tid; l < Ll; l += 128) {
        int r = user_hist[(size_t)uidx * Ll + l];
        bool ok = (r != tgt) && (r != NITEMS);
        sh_r[l] = ok ? r : -1;
        validf += ok ? 1.f : 0.f;
    }
    __syncthreads();

    float nvf = breduce_sum(validf, red);
    int n_valid = (int)(nvf + 0.5f);
    float nv_clamped = (n_valid > 0) ? (float)n_valid : 1.0f;
    float mu_p = -logf(nv_clamped);

    // per-lane q (bf16x2 pair) and v (fp32) loaded directly from gmem
    uint32_t qh0, qh1;
    float4 v4;
    {
        const float* qp = g_Q + (size_t)b * Dd + lane * 4;
        float4 qq = *(const float4*)qp;       // 16B aligned
        __nv_bfloat162 h0 = __floats2bfloat162_rn(qq.x, qq.y);
        __nv_bfloat162 h1 = __floats2bfloat162_rn(qq.z, qq.w);
        qh0 = *(uint32_t*)&h0;
        qh1 = *(uint32_t*)&h1;
        v4 = *(const float4*)(v_att + lane * 4);
    }

    // scores: warp per l, 4 rows/iteration; bf16x2 add+tanh, fp32 dot
    for (int l = wrp; l < Ll; l += 16) {
        int rs0 = sh_r[l];
        int rs1 = (l + 4  < Ll) ? sh_r[l + 4]  : -1;
        int rs2 = (l + 8  < Ll) ? sh_r[l + 8]  : -1;
        int rs3 = (l + 12 < Ll) ? sh_r[l + 12] : -1;
        uint2 raw0 = make_uint2(0u, 0u), raw1 = make_uint2(0u, 0u);
        uint2 raw2 = make_uint2(0u, 0u), raw3 = make_uint2(0u, 0u);
        if (rs0 >= 0) raw0 = ((const uint2*)(g_KWh + (size_t)rs0 * Dd))[lane];
        if (rs1 >= 0) raw1 = ((const uint2*)(g_KWh + (size_t)rs1 * Dd))[lane];
        if (rs2 >= 0) raw2 = ((const uint2*)(g_KWh + (size_t)rs2 * Dd))[lane];
        if (rs3 >= 0) raw3 = ((const uint2*)(g_KWh + (size_t)rs3 * Dd))[lane];

        float t0, t1, t2, t3;
#define SCORE_ROW(tv, raw) {                                                  \
            uint32_t h0 = btanh2(badd2(raw.x, qh0));                          \
            uint32_t h1 = btanh2(badd2(raw.y, qh1));                          \
            float2 f0 = __bfloat1622float2(*(__nv_bfloat162*)&h0);            \
            float2 f1 = __bfloat1622float2(*(__nv_bfloat162*)&h1);            \
            tv = v4.x * f0.x;                                                 \
            tv = fmaf(v4.y, f0.y, tv);                                        \
            tv = fmaf(v4.z, f1.x, tv);                                        \
            tv = fmaf(v4.w, f1.y, tv);                                        \
        }
        SCORE_ROW(t0, raw0)
        SCORE_ROW(t1, raw1)
        SCORE_ROW(t2, raw2)
        SCORE_ROW(t3, raw3)
#undef SCORE_ROW
#pragma unroll
        for (int o = 16; o; o >>= 1) {
            t0 += __shfl_down_sync(0xffffffffu, t0, o);
            t1 += __shfl_down_sync(0xffffffffu, t1, o);
            t2 += __shfl_down_sync(0xffffffffu, t2, o);
            t3 += __shfl_down_sync(0xffffffffu, t3, o);
        }
        if (lane == 0) {
            sh_s[l] = (rs0 >= 0) ? t0 * 0.25f : -1e30f;
            if (l + 4  < Ll) sh_s[l + 4]  = (rs1 >= 0) ? t1 * 0.25f : -1e30f;
            if (l + 8  < Ll) sh_s[l + 8]  = (rs2 >= 0) ? t2 * 0.25f : -1e30f;
            if (l + 12 < Ll) sh_s[l + 12] = (rs3 >= 0) ? t3 * 0.25f : -1e30f;
        }
    }
    __syncthreads();

    // softmax
    float m = -1e30f;
    for (int l = tid; l < Ll; l += 128) m = fmaxf(m, sh_s[l]);
    m = breduce_max(m, red);

    float esum = 0.f;
    for (int l = tid; l < Ll; l += 128) {
        float e = 0.f;
        if (sh_r[l] >= 0) e = expf(sh_s[l] - m);
        sh_s[l] = e;
        esum += e;
    }
    esum = breduce_sum(esum, red);
    float inv_es = (esum > 0.f) ? (1.0f / esum) : 0.f;

    // sampled weights via precomputed lognormal factors + KL; triple reduce
    float klacc = 0.f, s1 = 0.f, s2 = 0.f;
    for (int l = tid; l < Ll; l += 128) {
        float w1 = 0.f, w2 = 0.f;
        if (sh_r[l] >= 0) {
            float alpha = sh_s[l] * inv_es;
            float ap = alpha + 1e-24f;
            float mu = logf(ap);
            float2 F = g_F12[b * Ll + l];
            w1 = ap * F.x;
            w2 = ap * F.y;
            float dmu = mu - mu_p;
            klacc += 1.8075851f + 0.5f * dmu * dmu;  // log(10)-0.5+SIG_Q^2/2 + d^2/2
        }
        sh_w1[l] = w1;
        sh_w2[l] = w2;
        s1 += w1;
        s2 += w2;
    }
    breduce_sum3(klacc, s1, s2, red);
    if (tid == 0) { g_klp[b] = klacc; g_cnt[b] = n_valid; }
    float i1 = 1.0f / (s1 + 1e-12f);
    float i2 = 1.0f / (s2 + 1e-12f);

    // contexts: warp-per-row gather with LDG.128 (value path stays fp32)
    {
        float4 cu4 = make_float4(0.f, 0.f, 0.f, 0.f);
        float4 ci4 = make_float4(0.f, 0.f, 0.f, 0.f);
        const int lbase = wrp * 50;
#pragma unroll 5
        for (int j = 0; j < 50; j += 2) {
            int l0 = lbase + j, l1 = l0 + 1;
            int r0 = sh_r[l0], r1 = sh_r[l1];
            float4 v0 = make_float4(0.f, 0.f, 0.f, 0.f);
            float4 v1 = make_float4(0.f, 0.f, 0.f, 0.f);
            if (r0 >= 0) v0 = ((const float4*)(item_emb + (size_t)r0 * Dd))[lane];
            if (r1 >= 0) v1 = ((const float4*)(item_emb + (size_t)r1 * Dd))[lane];
            float w10 = sh_w1[l0], w20 = sh_w2[l0];
            float w11 = sh_w1[l1], w21 = sh_w2[l1];
            cu4.x = fmaf(w10, v0.x, fmaf(w11, v1.x, cu4.x));
            cu4.y = fmaf(w10, v0.y, fmaf(w11, v1.y, cu4.y));
            cu4.z = fmaf(w10, v0.z, fmaf(w11, v1.z, cu4.z));
            cu4.w = fmaf(w10, v0.w, fmaf(w11, v1.w, cu4.w));
            ci4.x = fmaf(w20, v0.x, fmaf(w21, v1.x, ci4.x));
            ci4.y = fmaf(w20, v0.y, fmaf(w21, v1.y, ci4.y));
            ci4.z = fmaf(w20, v0.z, fmaf(w21, v1.z, ci4.z));
            ci4.w = fmaf(w20, v0.w, fmaf(w21, v1.w, ci4.w));
        }
        *(float4*)&sred[0][wrp][lane * 4] = cu4;
        *(float4*)&sred[1][wrp][lane * 4] = ci4;
    }
    __syncthreads();
    float cu = (sred[0][0][tid] + sred[0][1][tid]) +
               (sred[0][2][tid] + sred[0][3][tid]);
    float ci = (sred[1][0][tid] + sred[1][1][tid]) +
               (sred[1][2][tid] + sred[1][3][tid]);
    cu *= i1; ci *= i2;

    // both layernorms via sum/sumsq, single 4-value reduce round
    float xu = cu * sh_u[tid];
    float xi = ci * item_emb[(size_t)tgt * Dd + tid];
    float su_ = xu, squ = xu * xu, si_ = xi, sqi = xi * xi;
    breduce_sum4(su_, squ, si_, sqi, red);
    float mean_u = su_ * (1.0f / Dd);
    float var_u  = squ * (1.0f / Dd) - mean_u * mean_u;
    float mean_i = si_ * (1.0f / Dd);
    float var_i  = sqi * (1.0f / Dd) - mean_i * mean_i;
    float us  = (xu - mean_u) * rsqrtf(var_u + 1e-5f) * ln_u_g[tid] + ln_u_b[tid];
    float is_ = (xi - mean_i) * rsqrtf(var_i + 1e-5f) * ln_i_g[tid] + ln_i_b[tid];

    float pv = us * is_ * pred_W[tid];
    float dot = breduce_sum(pv, red);
    if (tid == 0) out[b] = dot + pred_b[0];
}

// ------------------------------------------- Kernel D: deterministic KL reduce
__global__ __launch_bounds__(256) void kl_reduce_kernel(float* __restrict__ out,
                                                        int out_size) {
    __shared__ float rs[8];
    __shared__ int   ri[8];
    int tid = threadIdx.x;
    float s = 0.f; int c = 0;
    for (int i = tid; i < Bb; i += 256) { s += g_klp[i]; c += g_cnt[i]; }
#pragma unroll
    for (int o = 16; o; o >>= 1) {
        s += __shfl_down_sync(0xffffffffu, s, o);
        c += __shfl_down_sync(0xffffffffu, c, o);
    }
    if ((tid & 31) == 0) { rs[tid >> 5] = s; ri[tid >> 5] = c; }
    __syncthreads();
    if (tid == 0) {
        float S = 0.f; int C = 0;
        for (int i = 0; i < 8; i++) { S += rs[i]; C += ri[i]; }
        if (C < 1) C = 1;
        float kl = 0.25f * S / (float)C;   // BETA * sum / cnt ; (kl_u+kl_i)/2 == kl_u
        if (out_size > Bb) out[Bb] = kl;
    }
}

// ------------------------------------------- launcher
extern "C" void kernel_launch(void* const* d_in, const int* in_sizes, int n_in,
                              void* d_out, int out_size) {
    const float* user_emb = (const float*)d_in[0];
    const float* item_emb = (const float*)d_in[1];
    const float* Wq       = (const float*)d_in[2];
    const float* Wk       = (const float*)d_in[3];
    const float* b_att    = (const float*)d_in[4];
    const float* v_att    = (const float*)d_in[5];
    const float* ln_u_g   = (const float*)d_in[6];
    const float* ln_u_b   = (const float*)d_in[7];
    const float* ln_i_g   = (const float*)d_in[8];
    const float* ln_i_b   = (const float*)d_in[9];
    const float* pred_W   = (const float*)d_in[10];
    const float* pred_b   = (const float*)d_in[11];
    const int* user_hist  = (const int*)d_in[12];
    const int* user_idx   = (const int*)d_in[13];
    const int* item_idx   = (const int*)d_in[14];
    float* out = (float*)d_out;

    static cudaStream_t s1 = nullptr, s2 = nullptr;
    static cudaEvent_t evRoot = nullptr, ev1 = nullptr, ev2 = nullptr;
    if (s1 == nullptr) {
        cudaStreamCreateWithFlags(&s1, cudaStreamNonBlocking);
        cudaStreamCreateWithFlags(&s2, cudaStreamNonBlocking);
        cudaEventCreateWithFlags(&evRoot, cudaEventDisableTiming);
        cudaEventCreateWithFlags(&ev1, cudaEventDisableTiming);
        cudaEventCreateWithFlags(&ev2, cudaEventDisableTiming);
    }

    const int kw_smem = 128 * PADU * 4 + 2 * 64 * PADW * 4;   // 102400 B
    const int q_smem  = (128 + 32) * PADU * 4;                // 43520 B
    cudaFuncSetAttribute(kw_kernel, cudaFuncAttributeMaxDynamicSharedMemorySize,
                         kw_smem);
    cudaFuncSetAttribute(q_kernel, cudaFuncAttributeMaxDynamicSharedMemorySize,
                         q_smem);

    // fork: eps on s1, q on s2, kw on main stream
    cudaEventRecord(evRoot, 0);
    cudaStreamWaitEvent(s1, evRoot, 0);
    cudaStreamWaitEvent(s2, evRoot, 0);

    eps_kernel<<<(Bb * Ll + 255) / 256, 256, 0, s1>>>();
    q_kernel<<<Bb / 32, 256, q_smem, s2>>>(user_emb, user_idx, Wq, b_att);

    kw_kernel<<<KW_GRID, 256, kw_smem>>>(item_emb, Wk);

    // join
    cudaEventRecord(ev1, s1);
    cudaEventRecord(ev2, s2);
    cudaStreamWaitEvent(0, ev1, 0);
    cudaStreamWaitEvent(0, ev2, 0);

    fused_kernel<<<Bb, 128>>>(user_emb, item_emb, v_att,
                              ln_u_g, ln_u_b, ln_i_g, ln_i_b,
                              pred_W, pred_b, user_hist, user_idx, item_idx, out);
    kl_reduce_kernel<<<1, 256>>>(out, out_size);
}